// round 1
// baseline (speedup 1.0000x reference)
#include <cuda_runtime.h>
#include <math.h>

#define B_  1024
#define S_  256
#define H_  1024
#define E_  16
#define K_  4
#define HE_ 256
#define C_  3

// ---------------- device scratch (statically allocated; no cudaMalloc) -------
__device__ float g_pooled[B_*H_];              // 4 MB
__device__ float g_t[B_*H_];                   // 4 MB  tanh(cls@denseW^T+b)
__device__ float g_orig[B_*C_];
__device__ int   g_topi[B_*K_];
__device__ float g_topw[B_*K_];
__device__ int   g_cnt[E_];
__device__ int   g_tok[E_*B_];
__device__ int   g_slot[E_*B_];
__device__ float g_h[(size_t)E_*B_*HE_];       // 16 MB  post-LN-gelu hidden per assignment slot
__device__ float g_el[B_*K_*C_];               // expert logits per (token, k-slot)

// ---------------- 1) pooled mean over sequence -------------------------------
__global__ void __launch_bounds__(256) pool_kernel(const float* __restrict__ hid){
    int b = blockIdx.x;
    const float4* p = reinterpret_cast<const float4*>(hid + (size_t)b*S_*H_) + threadIdx.x;
    float ax=0.f,ay=0.f,az=0.f,aw=0.f;
    float bx=0.f,by=0.f,bz=0.f,bw=0.f;
    #pragma unroll 4
    for (int s=0; s<S_; s+=2){
        float4 v0 = p[(size_t)s*(H_/4)];
        float4 v1 = p[(size_t)(s+1)*(H_/4)];
        ax+=v0.x; ay+=v0.y; az+=v0.z; aw+=v0.w;
        bx+=v1.x; by+=v1.y; bz+=v1.z; bw+=v1.w;
    }
    float4 r;
    r.x=(ax+bx)*(1.f/S_); r.y=(ay+by)*(1.f/S_);
    r.z=(az+bz)*(1.f/S_); r.w=(aw+bw)*(1.f/S_);
    reinterpret_cast<float4*>(g_pooled + (size_t)b*H_)[threadIdx.x] = r;
}

// ---------------- 2) router logits + top-4 + softmax -------------------------
__global__ void __launch_bounds__(512) router_topk_kernel(const float* __restrict__ hid,
                                                          const float* __restrict__ rW,
                                                          const float* __restrict__ rb){
    __shared__ float cls[H_];
    __shared__ float lg[E_];
    int b = blockIdx.x, tid = threadIdx.x;
    cls[tid]       = hid[(size_t)b*S_*H_ + tid];
    cls[tid + 512] = hid[(size_t)b*S_*H_ + tid + 512];
    __syncthreads();
    int w = tid >> 5, lane = tid & 31;   // 16 warps = 16 experts
    float s = 0.f;
    const float* wr = rW + w*H_;
    #pragma unroll 8
    for (int j=lane; j<H_; j+=32) s += cls[j]*wr[j];
    #pragma unroll
    for (int o=16;o>0;o>>=1) s += __shfl_xor_sync(0xffffffffu, s, o);
    if (lane==0) lg[w] = s + rb[w];
    __syncthreads();
    if (tid==0){
        float v[E_];
        #pragma unroll
        for (int i=0;i<E_;i++) v[i]=lg[i];
        int   idxs[K_]; float vals[K_];
        for (int k=0;k<K_;k++){
            int bi=0; float bv=-3.0e38f;
            #pragma unroll
            for (int i=0;i<E_;i++){ if (v[i]>bv){ bv=v[i]; bi=i; } }
            idxs[k]=bi; vals[k]=bv; v[bi]=-3.0e38f;
        }
        float m = vals[0], ssum=0.f, wv[K_];
        for (int k=0;k<K_;k++){ wv[k]=expf(vals[k]-m); ssum+=wv[k]; }
        float inv = 1.f/ssum;
        for (int k=0;k<K_;k++){ g_topi[b*K_+k]=idxs[k]; g_topw[b*K_+k]=wv[k]*inv; }
    }
}

// ---------------- 3) expert assignment gather --------------------------------
__global__ void zero_cnt_kernel(){ if (threadIdx.x < E_) g_cnt[threadIdx.x]=0; }

__global__ void gather_kernel(){
    int idx = blockIdx.x*256 + threadIdx.x;
    if (idx >= B_*K_) return;
    int e = g_topi[idx];
    int pos = atomicAdd(&g_cnt[e], 1);
    g_tok [e*B_+pos] = idx >> 2;
    g_slot[e*B_+pos] = idx & 3;
}

// ---------------- 4) dense head GEMM: t = tanh(cls @ dW^T + db) --------------
// 64x64 tile, BK=16, 256 threads, 4x4 register tile
__global__ void __launch_bounds__(256) dense_tanh_kernel(const float* __restrict__ hid,
                                                         const float* __restrict__ W,
                                                         const float* __restrict__ bias){
    __shared__ float As[16][68];
    __shared__ float Bs[16][68];
    int tid = threadIdx.x;
    int tx = tid & 15, ty = tid >> 4;
    int m0 = blockIdx.y*64, n0 = blockIdx.x*64;
    int lr = tid >> 2, lq = tid & 3;
    float acc[4][4];
    #pragma unroll
    for (int i=0;i<4;i++)
        #pragma unroll
        for (int j=0;j<4;j++) acc[i][j]=0.f;
    const float* Arow = hid + (size_t)(m0+lr)*S_*H_ + lq*4;   // cls row (s=0)
    const float* Brow = W   + (size_t)(n0+lr)*H_   + lq*4;
    for (int k0=0; k0<H_; k0+=16){
        float4 a = *(const float4*)(Arow + k0);
        float4 b = *(const float4*)(Brow + k0);
        As[lq*4+0][lr]=a.x; As[lq*4+1][lr]=a.y; As[lq*4+2][lr]=a.z; As[lq*4+3][lr]=a.w;
        Bs[lq*4+0][lr]=b.x; Bs[lq*4+1][lr]=b.y; Bs[lq*4+2][lr]=b.z; Bs[lq*4+3][lr]=b.w;
        __syncthreads();
        #pragma unroll
        for (int k=0;k<16;k++){
            float4 av = *(const float4*)&As[k][ty*4];
            float4 bv = *(const float4*)&Bs[k][tx*4];
            float aa[4]={av.x,av.y,av.z,av.w};
            float bb[4]={bv.x,bv.y,bv.z,bv.w};
            #pragma unroll
            for (int i=0;i<4;i++)
                #pragma unroll
                for (int j=0;j<4;j++) acc[i][j] += aa[i]*bb[j];
        }
        __syncthreads();
    }
    float4 db4 = *(const float4*)&bias[n0+tx*4];
    float bb[4]={db4.x,db4.y,db4.z,db4.w};
    #pragma unroll
    for (int i=0;i<4;i++){
        float4 o;
        o.x = tanhf(acc[i][0]+bb[0]);
        o.y = tanhf(acc[i][1]+bb[1]);
        o.z = tanhf(acc[i][2]+bb[2]);
        o.w = tanhf(acc[i][3]+bb[3]);
        *(float4*)&g_t[(size_t)(m0+ty*4+i)*H_ + n0 + tx*4] = o;
    }
}

// ---------------- 5) orig = t @ out_W^T + out_b ------------------------------
__global__ void __launch_bounds__(256) orig_kernel(const float* __restrict__ oW,
                                                   const float* __restrict__ ob){
    int w = threadIdx.x >> 5, lane = threadIdx.x & 31;
    int b = blockIdx.x*8 + w;
    const float* t = g_t + (size_t)b*H_;
    for (int c=0;c<C_;c++){
        float s=0.f;
        const float* wr = oW + c*H_;
        #pragma unroll 8
        for (int j=lane; j<H_; j+=32) s += t[j]*wr[j];
        #pragma unroll
        for (int o=16;o>0;o>>=1) s += __shfl_xor_sync(0xffffffffu, s, o);
        if (lane==0) g_orig[b*C_+c] = s + ob[c];
    }
}

// ---------------- 6) expert GEMM1 (selected rows): h = gelu(LN(pooled@eW1^T+b))
// per block: 32 gathered rows x 256 cols, K=1024, BK=32; threads (tx 0..63, ty 0..3),
// 8x4 register tile. LN + GELU fused in epilogue (full N per block).
__global__ void __launch_bounds__(256) egemm1_kernel(const float* __restrict__ eW1,
                                                     const float* __restrict__ eb1,
                                                     const float* __restrict__ eg,
                                                     const float* __restrict__ ebt){
    int e = blockIdx.y;
    int n = g_cnt[e];
    int r0 = blockIdx.x*32;
    if (r0 >= n) return;
    __shared__ float Xs[32][36];
    __shared__ float Ws[32][256];
    __shared__ int   toks[32];
    __shared__ float mu[32], rsd[32];
    int tid = threadIdx.x;
    if (tid < 32){
        int r = r0 + tid;
        toks[tid] = g_tok[e*B_ + (r < n ? r : (n-1))];
    }
    __syncthreads();
    int tx = tid & 63, ty = tid >> 6;
    int xm = tid & 31, xq = tid >> 5;
    const float* wrow = eW1 + ((size_t)e*HE_ + tid)*H_;
    const float* xrow = g_pooled + (size_t)toks[xm]*H_;
    float acc[8][4];
    #pragma unroll
    for (int i=0;i<8;i++)
        #pragma unroll
        for (int j=0;j<4;j++) acc[i][j]=0.f;

    for (int k0=0; k0<H_; k0+=32){
        float4 xv = *(const float4*)(xrow + k0 + xq*4);
        Xs[xq*4+0][xm]=xv.x; Xs[xq*4+1][xm]=xv.y; Xs[xq*4+2][xm]=xv.z; Xs[xq*4+3][xm]=xv.w;
        #pragma unroll
        for (int q=0;q<8;q++){
            float4 wv = *(const float4*)(wrow + k0 + q*4);
            Ws[q*4+0][tid]=wv.x; Ws[q*4+1][tid]=wv.y; Ws[q*4+2][tid]=wv.z; Ws[q*4+3][tid]=wv.w;
        }
        __syncthreads();
        #pragma unroll
        for (int kk=0;kk<32;kk++){
            float4 wb = *(const float4*)&Ws[kk][tx*4];
            float4 x0 = *(const float4*)&Xs[kk][ty*8];
            float4 x1 = *(const float4*)&Xs[kk][ty*8+4];
            float xv8[8]={x0.x,x0.y,x0.z,x0.w,x1.x,x1.y,x1.z,x1.w};
            float wv4[4]={wb.x,wb.y,wb.z,wb.w};
            #pragma unroll
            for (int i=0;i<8;i++)
                #pragma unroll
                for (int j=0;j<4;j++) acc[i][j] += xv8[i]*wv4[j];
        }
        __syncthreads();
    }
    // epilogue: bias, LN stats across 256 cols, gelu, store
    float4 b1 = *(const float4*)&eb1[e*HE_ + tx*4];
    float bb[4]={b1.x,b1.y,b1.z,b1.w};
    float v[8][4], ps[8], pq[8];
    #pragma unroll
    for (int i=0;i<8;i++){
        ps[i]=0.f; pq[i]=0.f;
        #pragma unroll
        for (int j=0;j<4;j++){
            float t = acc[i][j]+bb[j];
            v[i][j]=t; ps[i]+=t; pq[i]+=t*t;
        }
    }
    float* red = &Ws[0][0];           // reuse 32 KB: sums [row*65+tx], sq at +2080
    #pragma unroll
    for (int i=0;i<8;i++){
        int row = ty*8+i;
        red[row*65+tx]       = ps[i];
        red[2080+row*65+tx]  = pq[i];
    }
    __syncthreads();
    if (tid < 32){
        float s=0.f, q=0.f;
        #pragma unroll 8
        for (int j=0;j<64;j++){ s += red[tid*65+j]; q += red[2080+tid*65+j]; }
        float m = s*(1.f/HE_);
        float var = q*(1.f/HE_) - m*m;
        mu[tid]=m; rsd[tid]=rsqrtf(var + 1e-5f);
    }
    __syncthreads();
    float4 gg4 = *(const float4*)&eg [e*HE_+tx*4];
    float4 bt4 = *(const float4*)&ebt[e*HE_+tx*4];
    float gga[4]={gg4.x,gg4.y,gg4.z,gg4.w};
    float bta[4]={bt4.x,bt4.y,bt4.z,bt4.w};
    #pragma unroll
    for (int i=0;i<8;i++){
        int row = ty*8+i, r = r0+row;
        if (r < n){
            float o[4];
            #pragma unroll
            for (int j=0;j<4;j++){
                float z = (v[i][j]-mu[row])*rsd[row]*gga[j] + bta[j];
                o[j] = 0.5f*z*(1.f+erff(z*0.70710678118654752f));
            }
            float4 o4; o4.x=o[0]; o4.y=o[1]; o4.z=o[2]; o4.w=o[3];
            *(float4*)&g_h[((size_t)e*B_ + r)*HE_ + tx*4] = o4;
        }
    }
}

// ---------------- 7) expert GEMM2 + fused proj: el = proj_W@(eW2@h+b2)+pb ---
__global__ void __launch_bounds__(256) egemm2_kernel(const float* __restrict__ eW2,
                                                     const float* __restrict__ eb2,
                                                     const float* __restrict__ pW,
                                                     const float* __restrict__ pb){
    int e = blockIdx.y;
    int n = g_cnt[e];
    int r0 = blockIdx.x*32;
    if (r0 >= n) return;
    __shared__ float Xs[32][36];
    __shared__ float Ws[32][256];
    __shared__ int   toks[32], slots[32];
    int tid = threadIdx.x;
    if (tid < 32){
        int r = r0 + tid;
        int rc = (r < n) ? r : (n-1);
        toks[tid]  = g_tok [e*B_+rc];
        slots[tid] = g_slot[e*B_+rc];
    }
    __syncthreads();
    int tx = tid & 63, ty = tid >> 6;
    int xm = tid & 31, xq = tid >> 5;
    int xr = r0+xm; if (xr >= n) xr = n-1;
    const float* xrow = g_h + ((size_t)e*B_ + xr)*HE_;
    const float* wrow = eW2 + ((size_t)e*HE_ + tid)*HE_;
    float acc[8][4];
    #pragma unroll
    for (int i=0;i<8;i++)
        #pragma unroll
        for (int j=0;j<4;j++) acc[i][j]=0.f;

    for (int k0=0; k0<HE_; k0+=32){
        float4 xv = *(const float4*)(xrow + k0 + xq*4);
        Xs[xq*4+0][xm]=xv.x; Xs[xq*4+1][xm]=xv.y; Xs[xq*4+2][xm]=xv.z; Xs[xq*4+3][xm]=xv.w;
        #pragma unroll
        for (int q=0;q<8;q++){
            float4 wv = *(const float4*)(wrow + k0 + q*4);
            Ws[q*4+0][tid]=wv.x; Ws[q*4+1][tid]=wv.y; Ws[q*4+2][tid]=wv.z; Ws[q*4+3][tid]=wv.w;
        }
        __syncthreads();
        #pragma unroll
        for (int kk=0;kk<32;kk++){
            float4 wb = *(const float4*)&Ws[kk][tx*4];
            float4 x0 = *(const float4*)&Xs[kk][ty*8];
            float4 x1 = *(const float4*)&Xs[kk][ty*8+4];
            float xv8[8]={x0.x,x0.y,x0.z,x0.w,x1.x,x1.y,x1.z,x1.w};
            float wv4[4]={wb.x,wb.y,wb.z,wb.w};
            #pragma unroll
            for (int i=0;i<8;i++)
                #pragma unroll
                for (int j=0;j<4;j++) acc[i][j] += xv8[i]*wv4[j];
        }
        __syncthreads();
    }
    // epilogue: +eb2 then project to C=3, block-reduce across 64 tx groups
    float4 b2 = *(const float4*)&eb2[e*HE_+tx*4];
    float bb[4]={b2.x,b2.y,b2.z,b2.w};
    float pwv[C_][4];
    #pragma unroll
    for (int cp=0;cp<C_;cp++)
        #pragma unroll
        for (int j=0;j<4;j++) pwv[cp][j] = pW[cp*HE_ + tx*4 + j];
    float p[8][C_];
    #pragma unroll
    for (int i=0;i<8;i++){
        p[i][0]=0.f; p[i][1]=0.f; p[i][2]=0.f;
        #pragma unroll
        for (int j=0;j<4;j++){
            float h2 = acc[i][j]+bb[j];
            #pragma unroll
            for (int cp=0;cp<C_;cp++) p[i][cp] += h2*pwv[cp][j];
        }
    }
    float* red = &Ws[0][0];   // layout: [cp*2080 + row*65 + tx]
    #pragma unroll
    for (int i=0;i<8;i++){
        int row = ty*8+i;
        #pragma unroll
        for (int cp=0;cp<C_;cp++) red[cp*2080 + row*65 + tx] = p[i][cp];
    }
    __syncthreads();
    if (tid < 32){
        int r = r0 + tid;
        if (r < n){
            int b = toks[tid], sl = slots[tid];
            #pragma unroll
            for (int cp=0;cp<C_;cp++){
                float s=0.f;
                #pragma unroll 8
                for (int j=0;j<64;j++) s += red[cp*2080 + tid*65 + j];
                g_el[(b*K_+sl)*C_+cp] = s + pb[cp];
            }
        }
    }
}

// ---------------- 8) final head: moe combine + f1 + LN + relu + f2 ----------
__global__ void __launch_bounds__(256) final_kernel(const float* __restrict__ f1W,
                                                    const float* __restrict__ f1b,
                                                    const float* __restrict__ fg,
                                                    const float* __restrict__ fbt,
                                                    const float* __restrict__ f2W,
                                                    const float* __restrict__ f2b,
                                                    float* __restrict__ out){
    int b = blockIdx.x*blockDim.x + threadIdx.x;
    if (b >= B_) return;
    float comb[2*C_];
    #pragma unroll
    for (int c=0;c<C_;c++) comb[c] = g_orig[b*C_+c];
    float moe[C_]={0.f,0.f,0.f};
    #pragma unroll
    for (int k=0;k<K_;k++){
        float w = g_topw[b*K_+k];
        const float* el = &g_el[(b*K_+k)*C_];
        #pragma unroll
        for (int c=0;c<C_;c++) moe[c] += w*el[c];
    }
    #pragma unroll
    for (int c=0;c<C_;c++) comb[C_+c]=moe[c];
    float y[C_];
    #pragma unroll
    for (int c=0;c<C_;c++){
        float s = f1b[c];
        #pragma unroll
        for (int j=0;j<2*C_;j++) s += comb[j]*f1W[c*(2*C_)+j];
        y[c]=s;
    }
    float m = (y[0]+y[1]+y[2])*(1.f/3.f);
    float d0=y[0]-m, d1=y[1]-m, d2=y[2]-m;
    float var = (d0*d0+d1*d1+d2*d2)*(1.f/3.f);
    float rs = rsqrtf(var + 1e-5f);
    float z[C_];
    #pragma unroll
    for (int c=0;c<C_;c++) z[c] = fmaxf(0.f, (y[c]-m)*rs*fg[c] + fbt[c]);
    #pragma unroll
    for (int c2=0;c2<C_;c2++){
        float s = f2b[c2];
        #pragma unroll
        for (int c=0;c<C_;c++) s += z[c]*f2W[c2*C_+c];
        out[b*C_+c2] = s;
    }
}

// ---------------- launch -----------------------------------------------------
extern "C" void kernel_launch(void* const* d_in, const int* in_sizes, int n_in,
                              void* d_out, int out_size){
    const float* hid = (const float*)d_in[0];
    const float* rW  = (const float*)d_in[1];
    const float* rb  = (const float*)d_in[2];
    const float* eW1 = (const float*)d_in[3];
    const float* eb1 = (const float*)d_in[4];
    const float* eg  = (const float*)d_in[5];
    const float* ebt = (const float*)d_in[6];
    const float* eW2 = (const float*)d_in[7];
    const float* eb2 = (const float*)d_in[8];
    const float* pW  = (const float*)d_in[9];
    const float* pb  = (const float*)d_in[10];
    const float* dW  = (const float*)d_in[11];
    const float* db  = (const float*)d_in[12];
    const float* oW  = (const float*)d_in[13];
    const float* ob  = (const float*)d_in[14];
    const float* f1W = (const float*)d_in[15];
    const float* f1b = (const float*)d_in[16];
    const float* fg  = (const float*)d_in[17];
    const float* fbt = (const float*)d_in[18];
    const float* f2W = (const float*)d_in[19];
    const float* f2b = (const float*)d_in[20];
    float* out = (float*)d_out;

    pool_kernel<<<B_, 256>>>(hid);
    router_topk_kernel<<<B_, 512>>>(hid, rW, rb);
    zero_cnt_kernel<<<1, 32>>>();
    gather_kernel<<<(B_*K_)/256, 256>>>();
    dense_tanh_kernel<<<dim3(16,16), 256>>>(hid, dW, db);
    orig_kernel<<<B_/8, 256>>>(oW, ob);
    egemm1_kernel<<<dim3(B_/32, E_), 256>>>(eW1, eb1, eg, ebt);
    egemm2_kernel<<<dim3(B_/32, E_), 256>>>(eW2, eb2, pW, pb);
    final_kernel<<<B_/256, 256>>>(f1W, f1b, fg, fbt, f2W, f2b, out);
}

// round 4
// speedup vs baseline: 1.2881x; 1.2881x over previous
#include <cuda_runtime.h>
#include <math.h>
#include <stdint.h>

#define B_  1024
#define S_  256
#define H_  1024
#define E_  16
#define K_  4
#define HE_ 256
#define C_  3

// ---------------- device scratch ---------------------------------------------
__device__ float g_pooled[B_*H_];
__device__ float g_t[B_*H_];
__device__ float g_orig[B_*C_];
__device__ int   g_topi[B_*K_];
__device__ float g_topw[B_*K_];
__device__ int   g_cnt[E_];
__device__ int   g_tok[E_*B_];
__device__ int   g_slot[E_*B_];
__device__ float g_h[(size_t)E_*B_*HE_];
__device__ float g_el[B_*K_*C_];

// ---------------- tf32 mma helpers -------------------------------------------
__device__ __forceinline__ void mma_tf32(float* c, const unsigned* a, const unsigned* b){
    asm volatile("mma.sync.aligned.m16n8k8.row.col.f32.tf32.tf32.f32 "
        "{%0,%1,%2,%3},{%4,%5,%6,%7},{%8,%9},{%0,%1,%2,%3};\n"
        : "+f"(c[0]), "+f"(c[1]), "+f"(c[2]), "+f"(c[3])
        : "r"(a[0]), "r"(a[1]), "r"(a[2]), "r"(a[3]), "r"(b[0]), "r"(b[1]));
}

__device__ __forceinline__ void split4(float4 v, float4& h, float4& l){
    h.x = __uint_as_float(__float_as_uint(v.x) & 0xffffe000u); l.x = v.x - h.x;
    h.y = __uint_as_float(__float_as_uint(v.y) & 0xffffe000u); l.y = v.y - h.y;
    h.z = __uint_as_float(__float_as_uint(v.z) & 0xffffe000u); l.z = v.z - h.z;
    h.w = __uint_as_float(__float_as_uint(v.w) & 0xffffe000u); l.w = v.w - h.w;
}

// warp tile 64(m) x 32(n), BK=32, 3xTF32. As/Bs row-stride 36 floats.
__device__ __forceinline__ void compute_k32(const float* __restrict__ AsH,
                                            const float* __restrict__ AsL,
                                            const float* __restrict__ BsH,
                                            const float* __restrict__ BsL,
                                            int wmBase, int wnBase, int lane,
                                            float (&acc)[4][4][4]){
    int g = lane >> 2, q = lane & 3;
    #pragma unroll
    for (int kk = 0; kk < 32; kk += 8){
        unsigned ah[4][4], al[4][4], bh[4][2], bl[4][2];
        #pragma unroll
        for (int mf = 0; mf < 4; mf++){
            int r = wmBase + mf*16 + g;
            const float* pH = AsH + r*36 + kk + q;
            const float* pL = AsL + r*36 + kk + q;
            ah[mf][0] = __float_as_uint(pH[0]);
            ah[mf][1] = __float_as_uint(pH[8*36]);
            ah[mf][2] = __float_as_uint(pH[4]);
            ah[mf][3] = __float_as_uint(pH[8*36+4]);
            al[mf][0] = __float_as_uint(pL[0]);
            al[mf][1] = __float_as_uint(pL[8*36]);
            al[mf][2] = __float_as_uint(pL[4]);
            al[mf][3] = __float_as_uint(pL[8*36+4]);
        }
        #pragma unroll
        for (int nf = 0; nf < 4; nf++){
            int nn = wnBase + nf*8 + g;
            const float* pH = BsH + nn*36 + kk + q;
            const float* pL = BsL + nn*36 + kk + q;
            bh[nf][0] = __float_as_uint(pH[0]);
            bh[nf][1] = __float_as_uint(pH[4]);
            bl[nf][0] = __float_as_uint(pL[0]);
            bl[nf][1] = __float_as_uint(pL[4]);
        }
        #pragma unroll
        for (int mf = 0; mf < 4; mf++)
            #pragma unroll
            for (int nf = 0; nf < 4; nf++){
                mma_tf32(acc[mf][nf], ah[mf], bh[nf]);
                mma_tf32(acc[mf][nf], ah[mf], bl[nf]);
                mma_tf32(acc[mf][nf], al[mf], bh[nf]);
            }
    }
}

// ---------------- 1) pooled mean ---------------------------------------------
__global__ void __launch_bounds__(256) pool_kernel(const float* __restrict__ hid){
    int b = blockIdx.x;
    const float4* p = reinterpret_cast<const float4*>(hid + (size_t)b*S_*H_) + threadIdx.x;
    float ax=0.f,ay=0.f,az=0.f,aw=0.f;
    float bx=0.f,by=0.f,bz=0.f,bw=0.f;
    #pragma unroll 4
    for (int s=0; s<S_; s+=2){
        float4 v0 = p[(size_t)s*(H_/4)];
        float4 v1 = p[(size_t)(s+1)*(H_/4)];
        ax+=v0.x; ay+=v0.y; az+=v0.z; aw+=v0.w;
        bx+=v1.x; by+=v1.y; bz+=v1.z; bw+=v1.w;
    }
    float4 r;
    r.x=(ax+bx)*(1.f/S_); r.y=(ay+by)*(1.f/S_);
    r.z=(az+bz)*(1.f/S_); r.w=(aw+bw)*(1.f/S_);
    reinterpret_cast<float4*>(g_pooled + (size_t)b*H_)[threadIdx.x] = r;
}

// ---------------- 2) router + top-4 + softmax --------------------------------
__global__ void __launch_bounds__(512) router_topk_kernel(const float* __restrict__ hid,
                                                          const float* __restrict__ rW,
                                                          const float* __restrict__ rb){
    __shared__ float cls[H_];
    __shared__ float lg[E_];
    int b = blockIdx.x, tid = threadIdx.x;
    cls[tid]       = hid[(size_t)b*S_*H_ + tid];
    cls[tid + 512] = hid[(size_t)b*S_*H_ + tid + 512];
    __syncthreads();
    int w = tid >> 5, lane = tid & 31;
    float s = 0.f;
    const float* wr = rW + w*H_;
    #pragma unroll 8
    for (int j=lane; j<H_; j+=32) s += cls[j]*wr[j];
    #pragma unroll
    for (int o=16;o>0;o>>=1) s += __shfl_xor_sync(0xffffffffu, s, o);
    if (lane==0) lg[w] = s + rb[w];
    __syncthreads();
    if (tid==0){
        float v[E_];
        #pragma unroll
        for (int i=0;i<E_;i++) v[i]=lg[i];
        int   idxs[K_]; float vals[K_];
        for (int k=0;k<K_;k++){
            int bi=0; float bv=-3.0e38f;
            #pragma unroll
            for (int i=0;i<E_;i++){ if (v[i]>bv){ bv=v[i]; bi=i; } }
            idxs[k]=bi; vals[k]=bv; v[bi]=-3.0e38f;
        }
        float m = vals[0], ssum=0.f, wv[K_];
        for (int k=0;k<K_;k++){ wv[k]=expf(vals[k]-m); ssum+=wv[k]; }
        float inv = 1.f/ssum;
        for (int k=0;k<K_;k++){ g_topi[b*K_+k]=idxs[k]; g_topw[b*K_+k]=wv[k]*inv; }
    }
}

// ---------------- 3) gather (single block, smem counters) --------------------
__global__ void __launch_bounds__(1024) gather_kernel(){
    __shared__ int cnt[E_];
    int t = threadIdx.x;
    if (t < E_) cnt[t] = 0;
    __syncthreads();
    #pragma unroll
    for (int i=0;i<4;i++){
        int idx = t + i*1024;
        int e = g_topi[idx];
        int pos = atomicAdd(&cnt[e], 1);
        g_tok [e*B_+pos] = idx >> 2;
        g_slot[e*B_+pos] = idx & 3;
    }
    __syncthreads();
    if (t < E_) g_cnt[t] = cnt[t];
}

// ---------------- 4) dense head: t = tanh(cls @ dW^T + db), 3xTF32 -----------
// block 128x128, 8 warps (2x4), warp 64x32, BK=32
__global__ void __launch_bounds__(256) dense_tanh_kernel(const float* __restrict__ hid,
                                                         const float* __restrict__ W,
                                                         const float* __restrict__ bias){
    extern __shared__ float sm[];
    float* AsH = sm;
    float* AsL = AsH + 128*36;
    float* BsH = AsL + 128*36;
    float* BsL = BsH + 128*36;
    int t = threadIdx.x, lane = t & 31, warp = t >> 5;
    int wm = warp >> 2, wn = warp & 3;
    int m0 = blockIdx.y*128, n0 = blockIdx.x*128;
    int lr = t >> 3, lc = (t & 7)*4;
    float acc[4][4][4];
    #pragma unroll
    for (int i=0;i<4;i++)
        #pragma unroll
        for (int j=0;j<4;j++)
            #pragma unroll
            for (int k=0;k<4;k++) acc[i][j][k]=0.f;

    float4 avA[4], avB[4];
    #pragma unroll
    for (int i=0;i<4;i++){
        avA[i] = *(const float4*)(hid + (size_t)(m0 + lr + 32*i)*S_*H_ + lc);
        avB[i] = *(const float4*)(W   + (size_t)(n0 + lr + 32*i)*H_   + lc);
    }
    for (int it=0; it<32; it++){
        #pragma unroll
        for (int i=0;i<4;i++){
            float4 h,l;
            split4(avA[i], h, l);
            *(float4*)(AsH + (lr+32*i)*36 + lc) = h;
            *(float4*)(AsL + (lr+32*i)*36 + lc) = l;
            split4(avB[i], h, l);
            *(float4*)(BsH + (lr+32*i)*36 + lc) = h;
            *(float4*)(BsL + (lr+32*i)*36 + lc) = l;
        }
        __syncthreads();
        if (it+1 < 32){
            int k0 = (it+1)*32;
            #pragma unroll
            for (int i=0;i<4;i++){
                avA[i] = *(const float4*)(hid + (size_t)(m0 + lr + 32*i)*S_*H_ + k0 + lc);
                avB[i] = *(const float4*)(W   + (size_t)(n0 + lr + 32*i)*H_   + k0 + lc);
            }
        }
        compute_k32(AsH, AsL, BsH, BsL, wm*64, wn*32, lane, acc);
        __syncthreads();
    }
    int g = lane>>2, q = lane&3;
    #pragma unroll
    for (int nf=0;nf<4;nf++){
        int col = n0 + wn*32 + nf*8 + 2*q;
        float2 bb = *(const float2*)&bias[col];
        #pragma unroll
        for (int mf=0;mf<4;mf++){
            int row = m0 + wm*64 + mf*16 + g;
            float2 o0, o1;
            o0.x = tanhf(acc[mf][nf][0]+bb.x); o0.y = tanhf(acc[mf][nf][1]+bb.y);
            o1.x = tanhf(acc[mf][nf][2]+bb.x); o1.y = tanhf(acc[mf][nf][3]+bb.y);
            *(float2*)&g_t[(size_t)row*H_ + col]     = o0;
            *(float2*)&g_t[(size_t)(row+8)*H_ + col] = o1;
        }
    }
}

// ---------------- 5) orig = t @ out_W^T + out_b ------------------------------
__global__ void __launch_bounds__(256) orig_kernel(const float* __restrict__ oW,
                                                   const float* __restrict__ ob){
    int w = threadIdx.x >> 5, lane = threadIdx.x & 31;
    int b = blockIdx.x*8 + w;
    const float* t = g_t + (size_t)b*H_;
    for (int c=0;c<C_;c++){
        float s=0.f;
        const float* wr = oW + c*H_;
        #pragma unroll 8
        for (int j=lane; j<H_; j+=32) s += t[j]*wr[j];
        #pragma unroll
        for (int o=16;o>0;o>>=1) s += __shfl_xor_sync(0xffffffffu, s, o);
        if (lane==0) g_orig[b*C_+c] = s + ob[c];
    }
}

// ---------------- 6) expert GEMM1 + LN + GELU, 3xTF32 ------------------------
// block 64(gathered rows) x 256, 8 warps (1x8), warp 64x32, BK=32, K=1024
__global__ void __launch_bounds__(256) egemm1_kernel(const float* __restrict__ eW1,
                                                     const float* __restrict__ eb1,
                                                     const float* __restrict__ eg,
                                                     const float* __restrict__ ebt){
    extern __shared__ float sm[];
    float* AsH = sm;
    float* AsL = AsH + 64*36;
    float* BsH = AsL + 64*36;
    float* BsL = BsH + 256*36;
    float* Cs  = sm;                    // reused after mainloop, stride 260
    __shared__ int toks[64];
    int e = blockIdx.y;
    int n = g_cnt[e];
    int r0 = blockIdx.x*64;
    if (r0 >= n) return;
    int t = threadIdx.x, lane = t & 31, warp = t >> 5;
    if (t < 64) toks[t] = g_tok[e*B_ + min(r0 + t, n-1)];
    __syncthreads();
    int lr = t >> 3, lc = (t & 7)*4;
    float acc[4][4][4];
    #pragma unroll
    for (int i=0;i<4;i++)
        #pragma unroll
        for (int j=0;j<4;j++)
            #pragma unroll
            for (int k=0;k<4;k++) acc[i][j][k]=0.f;

    const float* wbase = eW1 + (size_t)e*HE_*H_;
    float4 avA[2], avB[8];
    #pragma unroll
    for (int i=0;i<2;i++)
        avA[i] = *(const float4*)(g_pooled + (size_t)toks[lr+32*i]*H_ + lc);
    #pragma unroll
    for (int i=0;i<8;i++)
        avB[i] = *(const float4*)(wbase + (size_t)(lr+32*i)*H_ + lc);

    for (int it=0; it<32; it++){
        #pragma unroll
        for (int i=0;i<2;i++){
            float4 h,l; split4(avA[i], h, l);
            *(float4*)(AsH + (lr+32*i)*36 + lc) = h;
            *(float4*)(AsL + (lr+32*i)*36 + lc) = l;
        }
        #pragma unroll
        for (int i=0;i<8;i++){
            float4 h,l; split4(avB[i], h, l);
            *(float4*)(BsH + (lr+32*i)*36 + lc) = h;
            *(float4*)(BsL + (lr+32*i)*36 + lc) = l;
        }
        __syncthreads();
        if (it+1 < 32){
            int k0 = (it+1)*32;
            #pragma unroll
            for (int i=0;i<2;i++)
                avA[i] = *(const float4*)(g_pooled + (size_t)toks[lr+32*i]*H_ + k0 + lc);
            #pragma unroll
            for (int i=0;i<8;i++)
                avB[i] = *(const float4*)(wbase + (size_t)(lr+32*i)*H_ + k0 + lc);
        }
        compute_k32(AsH, AsL, BsH, BsL, 0, warp*32, lane, acc);
        __syncthreads();
    }
    // stash C tile in smem (overwrites As/Bs)
    int g = lane>>2, q = lane&3;
    #pragma unroll
    for (int nf=0;nf<4;nf++){
        int col = warp*32 + nf*8 + 2*q;
        #pragma unroll
        for (int mf=0;mf<4;mf++){
            int row = mf*16 + g;
            float2 a; a.x=acc[mf][nf][0]; a.y=acc[mf][nf][1];
            float2 b; b.x=acc[mf][nf][2]; b.y=acc[mf][nf][3];
            *(float2*)&Cs[row*260 + col]     = a;
            *(float2*)&Cs[(row+8)*260 + col] = b;
        }
    }
    __syncthreads();
    // LN + GELU epilogue: 4 threads per row, 64 cols each
    int j = t & 3, row = t >> 2;
    int gr = r0 + row;
    const float* b1 = eb1 + e*HE_;
    float s = 0.f, qs = 0.f;
    #pragma unroll
    for (int cc=0; cc<64; cc+=4){
        float4 v = *(float4*)&Cs[row*260 + j*64 + cc];
        float4 bb = *(const float4*)&b1[j*64 + cc];
        v.x+=bb.x; v.y+=bb.y; v.z+=bb.z; v.w+=bb.w;
        s  += v.x+v.y+v.z+v.w;
        qs += v.x*v.x+v.y*v.y+v.z*v.z+v.w*v.w;
    }
    s  += __shfl_xor_sync(0xffffffffu, s, 1);  s  += __shfl_xor_sync(0xffffffffu, s, 2);
    qs += __shfl_xor_sync(0xffffffffu, qs, 1); qs += __shfl_xor_sync(0xffffffffu, qs, 2);
    float m = s*(1.f/HE_);
    float var = qs*(1.f/HE_) - m*m;
    float rstd = rsqrtf(var + 1e-5f);
    if (gr < n){
        float* outp = g_h + ((size_t)e*B_ + gr)*HE_ + j*64;
        const float* gp = eg  + e*HE_ + j*64;
        const float* bp = ebt + e*HE_ + j*64;
        #pragma unroll
        for (int cc=0; cc<64; cc+=4){
            float4 v = *(float4*)&Cs[row*260 + j*64 + cc];
            float4 bb = *(const float4*)&b1[j*64 + cc];
            float4 gg = *(const float4*)&gp[cc];
            float4 bt = *(const float4*)&bp[cc];
            float z0 = (v.x+bb.x-m)*rstd*gg.x + bt.x;
            float z1 = (v.y+bb.y-m)*rstd*gg.y + bt.y;
            float z2 = (v.z+bb.z-m)*rstd*gg.z + bt.z;
            float z3 = (v.w+bb.w-m)*rstd*gg.w + bt.w;
            float4 o;
            o.x = 0.5f*z0*(1.f+erff(z0*0.70710678118654752f));
            o.y = 0.5f*z1*(1.f+erff(z1*0.70710678118654752f));
            o.z = 0.5f*z2*(1.f+erff(z2*0.70710678118654752f));
            o.w = 0.5f*z3*(1.f+erff(z3*0.70710678118654752f));
            *(float4*)&outp[cc] = o;
        }
    }
}

// ---------------- 7) expert GEMM2 + fused proj, 3xTF32 -----------------------
// block 64x256, K=256 (8 iters)
__global__ void __launch_bounds__(256) egemm2_kernel(const float* __restrict__ eW2,
                                                     const float* __restrict__ eb2,
                                                     const float* __restrict__ pW,
                                                     const float* __restrict__ pb){
    extern __shared__ float sm[];
    float* AsH = sm;
    float* AsL = AsH + 64*36;
    float* BsH = AsL + 64*36;
    float* BsL = BsH + 256*36;
    float* Cs  = sm;
    __shared__ int toks[64], slots[64];
    int e = blockIdx.y;
    int n = g_cnt[e];
    int r0 = blockIdx.x*64;
    if (r0 >= n) return;
    int t = threadIdx.x, lane = t & 31, warp = t >> 5;
    if (t < 64){
        int rc = min(r0 + t, n-1);
        toks[t]  = g_tok [e*B_+rc];
        slots[t] = g_slot[e*B_+rc];
    }
    __syncthreads();
    int lr = t >> 3, lc = (t & 7)*4;
    float acc[4][4][4];
    #pragma unroll
    for (int i=0;i<4;i++)
        #pragma unroll
        for (int j=0;j<4;j++)
            #pragma unroll
            for (int k=0;k<4;k++) acc[i][j][k]=0.f;

    const float* wbase = eW2 + (size_t)e*HE_*HE_;
    const float* abase = g_h + (size_t)e*B_*HE_;
    int ar0 = min(r0 + lr,      n-1);
    int ar1 = min(r0 + lr + 32, n-1);
    float4 avA[2], avB[8];
    avA[0] = *(const float4*)(abase + (size_t)ar0*HE_ + lc);
    avA[1] = *(const float4*)(abase + (size_t)ar1*HE_ + lc);
    #pragma unroll
    for (int i=0;i<8;i++)
        avB[i] = *(const float4*)(wbase + (size_t)(lr+32*i)*HE_ + lc);

    for (int it=0; it<8; it++){
        {
            float4 h,l;
            split4(avA[0], h, l);
            *(float4*)(AsH + lr*36 + lc) = h;
            *(float4*)(AsL + lr*36 + lc) = l;
            split4(avA[1], h, l);
            *(float4*)(AsH + (lr+32)*36 + lc) = h;
            *(float4*)(AsL + (lr+32)*36 + lc) = l;
        }
        #pragma unroll
        for (int i=0;i<8;i++){
            float4 h,l; split4(avB[i], h, l);
            *(float4*)(BsH + (lr+32*i)*36 + lc) = h;
            *(float4*)(BsL + (lr+32*i)*36 + lc) = l;
        }
        __syncthreads();
        if (it+1 < 8){
            int k0 = (it+1)*32;
            avA[0] = *(const float4*)(abase + (size_t)ar0*HE_ + k0 + lc);
            avA[1] = *(const float4*)(abase + (size_t)ar1*HE_ + k0 + lc);
            #pragma unroll
            for (int i=0;i<8;i++)
                avB[i] = *(const float4*)(wbase + (size_t)(lr+32*i)*HE_ + k0 + lc);
        }
        compute_k32(AsH, AsL, BsH, BsL, 0, warp*32, lane, acc);
        __syncthreads();
    }
    int g = lane>>2, q = lane&3;
    #pragma unroll
    for (int nf=0;nf<4;nf++){
        int col = warp*32 + nf*8 + 2*q;
        #pragma unroll
        for (int mf=0;mf<4;mf++){
            int row = mf*16 + g;
            float2 a; a.x=acc[mf][nf][0]; a.y=acc[mf][nf][1];
            float2 b; b.x=acc[mf][nf][2]; b.y=acc[mf][nf][3];
            *(float2*)&Cs[row*260 + col]     = a;
            *(float2*)&Cs[(row+8)*260 + col] = b;
        }
    }
    __syncthreads();
    // proj epilogue: 4 threads/row, project 256 -> C=3
    int j = t & 3, row = t >> 2;
    int gr = r0 + row;
    const float* b2 = eb2 + e*HE_;
    float p0=0.f, p1=0.f, p2=0.f;
    #pragma unroll
    for (int cc=0; cc<64; cc+=4){
        float4 v = *(float4*)&Cs[row*260 + j*64 + cc];
        float4 bb = *(const float4*)&b2[j*64 + cc];
        v.x+=bb.x; v.y+=bb.y; v.z+=bb.z; v.w+=bb.w;
        float4 w0 = *(const float4*)&pW[0*HE_ + j*64 + cc];
        float4 w1 = *(const float4*)&pW[1*HE_ + j*64 + cc];
        float4 w2 = *(const float4*)&pW[2*HE_ + j*64 + cc];
        p0 += v.x*w0.x + v.y*w0.y + v.z*w0.z + v.w*w0.w;
        p1 += v.x*w1.x + v.y*w1.y + v.z*w1.z + v.w*w1.w;
        p2 += v.x*w2.x + v.y*w2.y + v.z*w2.z + v.w*w2.w;
    }
    p0 += __shfl_xor_sync(0xffffffffu, p0, 1); p0 += __shfl_xor_sync(0xffffffffu, p0, 2);
    p1 += __shfl_xor_sync(0xffffffffu, p1, 1); p1 += __shfl_xor_sync(0xffffffffu, p1, 2);
    p2 += __shfl_xor_sync(0xffffffffu, p2, 1); p2 += __shfl_xor_sync(0xffffffffu, p2, 2);
    if (j == 0 && gr < n){
        int b = toks[row], sl = slots[row];
        float* o = &g_el[(b*K_+sl)*C_];
        o[0] = p0 + pb[0];
        o[1] = p1 + pb[1];
        o[2] = p2 + pb[2];
    }
}

// ---------------- 8) final head ---------------------------------------------
__global__ void __launch_bounds__(256) final_kernel(const float* __restrict__ f1W,
                                                    const float* __restrict__ f1b,
                                                    const float* __restrict__ fg,
                                                    const float* __restrict__ fbt,
                                                    const float* __restrict__ f2W,
                                                    const float* __restrict__ f2b,
                                                    float* __restrict__ out){
    int b = blockIdx.x*blockDim.x + threadIdx.x;
    if (b >= B_) return;
    float comb[2*C_];
    #pragma unroll
    for (int c=0;c<C_;c++) comb[c] = g_orig[b*C_+c];
    float moe[C_]={0.f,0.f,0.f};
    #pragma unroll
    for (int k=0;k<K_;k++){
        float w = g_topw[b*K_+k];
        const float* el = &g_el[(b*K_+k)*C_];
        #pragma unroll
        for (int c=0;c<C_;c++) moe[c] += w*el[c];
    }
    #pragma unroll
    for (int c=0;c<C_;c++) comb[C_+c]=moe[c];
    float y[C_];
    #pragma unroll
    for (int c=0;c<C_;c++){
        float s = f1b[c];
        #pragma unroll
        for (int jj=0;jj<2*C_;jj++) s += comb[jj]*f1W[c*(2*C_)+jj];
        y[c]=s;
    }
    float m = (y[0]+y[1]+y[2])*(1.f/3.f);
    float d0=y[0]-m, d1=y[1]-m, d2=y[2]-m;
    float var = (d0*d0+d1*d1+d2*d2)*(1.f/3.f);
    float rs = rsqrtf(var + 1e-5f);
    float z[C_];
    #pragma unroll
    for (int c=0;c<C_;c++) z[c] = fmaxf(0.f, (y[c]-m)*rs*fg[c] + fbt[c]);
    #pragma unroll
    for (int c2=0;c2<C_;c2++){
        float s = f2b[c2];
        #pragma unroll
        for (int c=0;c<C_;c++) s += z[c]*f2W[c2*C_+c];
        out[b*C_+c2] = s;
    }
}

// ---------------- launch -----------------------------------------------------
extern "C" void kernel_launch(void* const* d_in, const int* in_sizes, int n_in,
                              void* d_out, int out_size){
    const float* hid = (const float*)d_in[0];
    const float* rW  = (const float*)d_in[1];
    const float* rb  = (const float*)d_in[2];
    const float* eW1 = (const float*)d_in[3];
    const float* eb1 = (const float*)d_in[4];
    const float* eg  = (const float*)d_in[5];
    const float* ebt = (const float*)d_in[6];
    const float* eW2 = (const float*)d_in[7];
    const float* eb2 = (const float*)d_in[8];
    const float* pW  = (const float*)d_in[9];
    const float* pb  = (const float*)d_in[10];
    const float* dW  = (const float*)d_in[11];
    const float* db  = (const float*)d_in[12];
    const float* oW  = (const float*)d_in[13];
    const float* ob  = (const float*)d_in[14];
    const float* f1W = (const float*)d_in[15];
    const float* f1b = (const float*)d_in[16];
    const float* fg  = (const float*)d_in[17];
    const float* fbt = (const float*)d_in[18];
    const float* f2W = (const float*)d_in[19];
    const float* f2b = (const float*)d_in[20];
    float* out = (float*)d_out;

    const int DSM_DENSE = 4*128*36*4;            // 73728 B
    const int DSM_EG    = (2*64*36 + 2*256*36)*4; // 92160 B
    cudaFuncSetAttribute(dense_tanh_kernel, cudaFuncAttributeMaxDynamicSharedMemorySize, DSM_DENSE);
    cudaFuncSetAttribute(egemm1_kernel,     cudaFuncAttributeMaxDynamicSharedMemorySize, DSM_EG);
    cudaFuncSetAttribute(egemm2_kernel,     cudaFuncAttributeMaxDynamicSharedMemorySize, DSM_EG);

    pool_kernel<<<B_, 256>>>(hid);
    router_topk_kernel<<<B_, 512>>>(hid, rW, rb);
    gather_kernel<<<1, 1024>>>();
    dense_tanh_kernel<<<dim3(8,8), 256, DSM_DENSE>>>(hid, dW, db);
    orig_kernel<<<B_/8, 256>>>(oW, ob);
    egemm1_kernel<<<dim3(B_/64, E_), 256, DSM_EG>>>(eW1, eb1, eg, ebt);
    egemm2_kernel<<<dim3(B_/64, E_), 256, DSM_EG>>>(eW2, eb2, pW, pb);
    final_kernel<<<B_/256, 256>>>(f1W, f1b, fg, fbt, f2W, f2b, out);
}

// round 5
// speedup vs baseline: 1.3633x; 1.0584x over previous
#include <cuda_runtime.h>
#include <math.h>
#include <stdint.h>

#define B_  1024
#define S_  256
#define H_  1024
#define E_  16
#define K_  4
#define HE_ 256
#define C_  3

// ---------------- device scratch ---------------------------------------------
__device__ float g_pooled[B_*H_];
__device__ float g_t[B_*H_];
__device__ float g_orig[B_*C_];
__device__ int   g_topi[B_*K_];
__device__ float g_topw[B_*K_];
__device__ int   g_cnt[E_];
__device__ int   g_tok[E_*B_];
__device__ int   g_slot[E_*B_];
__device__ float g_h[(size_t)E_*B_*HE_];
__device__ float g_el[B_*K_*C_];

// ---------------- tf32 mma helpers -------------------------------------------
__device__ __forceinline__ void mma_tf32(float* c, const unsigned* a, const unsigned* b){
    asm volatile("mma.sync.aligned.m16n8k8.row.col.f32.tf32.tf32.f32 "
        "{%0,%1,%2,%3},{%4,%5,%6,%7},{%8,%9},{%0,%1,%2,%3};\n"
        : "+f"(c[0]), "+f"(c[1]), "+f"(c[2]), "+f"(c[3])
        : "r"(a[0]), "r"(a[1]), "r"(a[2]), "r"(a[3]), "r"(b[0]), "r"(b[1]));
}

__device__ __forceinline__ void split4(float4 v, float4& h, float4& l){
    h.x = __uint_as_float(__float_as_uint(v.x) & 0xffffe000u); l.x = v.x - h.x;
    h.y = __uint_as_float(__float_as_uint(v.y) & 0xffffe000u); l.y = v.y - h.y;
    h.z = __uint_as_float(__float_as_uint(v.z) & 0xffffe000u); l.z = v.z - h.z;
    h.w = __uint_as_float(__float_as_uint(v.w) & 0xffffe000u); l.w = v.w - h.w;
}

// warp tile 64(m) x 32(n), BK=32, 3xTF32. As/Bs row-stride 36 floats.
__device__ __forceinline__ void compute_k32(const float* __restrict__ AsH,
                                            const float* __restrict__ AsL,
                                            const float* __restrict__ BsH,
                                            const float* __restrict__ BsL,
                                            int wmBase, int wnBase, int lane,
                                            float (&acc)[4][4][4]){
    int g = lane >> 2, q = lane & 3;
    #pragma unroll
    for (int kk = 0; kk < 32; kk += 8){
        unsigned ah[4][4], al[4][4], bh[4][2], bl[4][2];
        #pragma unroll
        for (int mf = 0; mf < 4; mf++){
            int r = wmBase + mf*16 + g;
            const float* pH = AsH + r*36 + kk + q;
            const float* pL = AsL + r*36 + kk + q;
            ah[mf][0] = __float_as_uint(pH[0]);
            ah[mf][1] = __float_as_uint(pH[8*36]);
            ah[mf][2] = __float_as_uint(pH[4]);
            ah[mf][3] = __float_as_uint(pH[8*36+4]);
            al[mf][0] = __float_as_uint(pL[0]);
            al[mf][1] = __float_as_uint(pL[8*36]);
            al[mf][2] = __float_as_uint(pL[4]);
            al[mf][3] = __float_as_uint(pL[8*36+4]);
        }
        #pragma unroll
        for (int nf = 0; nf < 4; nf++){
            int nn = wnBase + nf*8 + g;
            const float* pH = BsH + nn*36 + kk + q;
            const float* pL = BsL + nn*36 + kk + q;
            bh[nf][0] = __float_as_uint(pH[0]);
            bh[nf][1] = __float_as_uint(pH[4]);
            bl[nf][0] = __float_as_uint(pL[0]);
            bl[nf][1] = __float_as_uint(pL[4]);
        }
        #pragma unroll
        for (int mf = 0; mf < 4; mf++)
            #pragma unroll
            for (int nf = 0; nf < 4; nf++){
                mma_tf32(acc[mf][nf], ah[mf], bh[nf]);
                mma_tf32(acc[mf][nf], ah[mf], bl[nf]);
                mma_tf32(acc[mf][nf], al[mf], bh[nf]);
            }
    }
}

// ---------------- 1) pooled mean ---------------------------------------------
__global__ void __launch_bounds__(256) pool_kernel(const float* __restrict__ hid){
    int b = blockIdx.x;
    const float4* p = reinterpret_cast<const float4*>(hid + (size_t)b*S_*H_) + threadIdx.x;
    float ax=0.f,ay=0.f,az=0.f,aw=0.f;
    float bx=0.f,by=0.f,bz=0.f,bw=0.f;
    #pragma unroll 4
    for (int s=0; s<S_; s+=2){
        float4 v0 = p[(size_t)s*(H_/4)];
        float4 v1 = p[(size_t)(s+1)*(H_/4)];
        ax+=v0.x; ay+=v0.y; az+=v0.z; aw+=v0.w;
        bx+=v1.x; by+=v1.y; bz+=v1.z; bw+=v1.w;
    }
    float4 r;
    r.x=(ax+bx)*(1.f/S_); r.y=(ay+by)*(1.f/S_);
    r.z=(az+bz)*(1.f/S_); r.w=(aw+bw)*(1.f/S_);
    reinterpret_cast<float4*>(g_pooled + (size_t)b*H_)[threadIdx.x] = r;
}

// ---------------- 2) router + top-4 + softmax --------------------------------
__global__ void __launch_bounds__(512) router_topk_kernel(const float* __restrict__ hid,
                                                          const float* __restrict__ rW,
                                                          const float* __restrict__ rb){
    __shared__ float cls[H_];
    __shared__ float lg[E_];
    int b = blockIdx.x, tid = threadIdx.x;
    cls[tid]       = hid[(size_t)b*S_*H_ + tid];
    cls[tid + 512] = hid[(size_t)b*S_*H_ + tid + 512];
    __syncthreads();
    int w = tid >> 5, lane = tid & 31;
    float s = 0.f;
    const float* wr = rW + w*H_;
    #pragma unroll 8
    for (int j=lane; j<H_; j+=32) s += cls[j]*wr[j];
    #pragma unroll
    for (int o=16;o>0;o>>=1) s += __shfl_xor_sync(0xffffffffu, s, o);
    if (lane==0) lg[w] = s + rb[w];
    __syncthreads();
    if (tid==0){
        float v[E_];
        #pragma unroll
        for (int i=0;i<E_;i++) v[i]=lg[i];
        int   idxs[K_]; float vals[K_];
        for (int k=0;k<K_;k++){
            int bi=0; float bv=-3.0e38f;
            #pragma unroll
            for (int i=0;i<E_;i++){ if (v[i]>bv){ bv=v[i]; bi=i; } }
            idxs[k]=bi; vals[k]=bv; v[bi]=-3.0e38f;
        }
        float m = vals[0], ssum=0.f, wv[K_];
        for (int k=0;k<K_;k++){ wv[k]=expf(vals[k]-m); ssum+=wv[k]; }
        float inv = 1.f/ssum;
        for (int k=0;k<K_;k++){ g_topi[b*K_+k]=idxs[k]; g_topw[b*K_+k]=wv[k]*inv; }
    }
}

// ---------------- 3) gather (single block, smem counters) --------------------
__global__ void __launch_bounds__(1024) gather_kernel(){
    __shared__ int cnt[E_];
    int t = threadIdx.x;
    if (t < E_) cnt[t] = 0;
    __syncthreads();
    #pragma unroll
    for (int i=0;i<4;i++){
        int idx = t + i*1024;
        int e = g_topi[idx];
        int pos = atomicAdd(&cnt[e], 1);
        g_tok [e*B_+pos] = idx >> 2;
        g_slot[e*B_+pos] = idx & 3;
    }
    __syncthreads();
    if (t < E_) g_cnt[t] = cnt[t];
}

// ---------------- 4) dense head: t = tanh(cls @ dW^T + db), 3xTF32 -----------
// block 128x128, 8 warps (2x4), warp 64x32, BK=32
__global__ void __launch_bounds__(256) dense_tanh_kernel(const float* __restrict__ hid,
                                                         const float* __restrict__ W,
                                                         const float* __restrict__ bias){
    extern __shared__ float sm[];
    float* AsH = sm;
    float* AsL = AsH + 128*36;
    float* BsH = AsL + 128*36;
    float* BsL = BsH + 128*36;
    int t = threadIdx.x, lane = t & 31, warp = t >> 5;
    int wm = warp >> 2, wn = warp & 3;
    int m0 = blockIdx.y*128, n0 = blockIdx.x*128;
    int lr = t >> 3, lc = (t & 7)*4;
    float acc[4][4][4];
    #pragma unroll
    for (int i=0;i<4;i++)
        #pragma unroll
        for (int j=0;j<4;j++)
            #pragma unroll
            for (int k=0;k<4;k++) acc[i][j][k]=0.f;

    float4 avA[4], avB[4];
    #pragma unroll
    for (int i=0;i<4;i++){
        avA[i] = *(const float4*)(hid + (size_t)(m0 + lr + 32*i)*S_*H_ + lc);
        avB[i] = *(const float4*)(W   + (size_t)(n0 + lr + 32*i)*H_   + lc);
    }
    for (int it=0; it<32; it++){
        #pragma unroll
        for (int i=0;i<4;i++){
            float4 h,l;
            split4(avA[i], h, l);
            *(float4*)(AsH + (lr+32*i)*36 + lc) = h;
            *(float4*)(AsL + (lr+32*i)*36 + lc) = l;
            split4(avB[i], h, l);
            *(float4*)(BsH + (lr+32*i)*36 + lc) = h;
            *(float4*)(BsL + (lr+32*i)*36 + lc) = l;
        }
        __syncthreads();
        if (it+1 < 32){
            int k0 = (it+1)*32;
            #pragma unroll
            for (int i=0;i<4;i++){
                avA[i] = *(const float4*)(hid + (size_t)(m0 + lr + 32*i)*S_*H_ + k0 + lc);
                avB[i] = *(const float4*)(W   + (size_t)(n0 + lr + 32*i)*H_   + k0 + lc);
            }
        }
        compute_k32(AsH, AsL, BsH, BsL, wm*64, wn*32, lane, acc);
        __syncthreads();
    }
    int g = lane>>2, q = lane&3;
    #pragma unroll
    for (int nf=0;nf<4;nf++){
        int col = n0 + wn*32 + nf*8 + 2*q;
        float2 bb = *(const float2*)&bias[col];
        #pragma unroll
        for (int mf=0;mf<4;mf++){
            int row = m0 + wm*64 + mf*16 + g;
            float2 o0, o1;
            o0.x = tanhf(acc[mf][nf][0]+bb.x); o0.y = tanhf(acc[mf][nf][1]+bb.y);
            o1.x = tanhf(acc[mf][nf][2]+bb.x); o1.y = tanhf(acc[mf][nf][3]+bb.y);
            *(float2*)&g_t[(size_t)row*H_ + col]     = o0;
            *(float2*)&g_t[(size_t)(row+8)*H_ + col] = o1;
        }
    }
}

// ---------------- 5) orig = t @ out_W^T + out_b ------------------------------
__global__ void __launch_bounds__(256) orig_kernel(const float* __restrict__ oW,
                                                   const float* __restrict__ ob){
    int w = threadIdx.x >> 5, lane = threadIdx.x & 31;
    int b = blockIdx.x*8 + w;
    const float* t = g_t + (size_t)b*H_;
    for (int c=0;c<C_;c++){
        float s=0.f;
        const float* wr = oW + c*H_;
        #pragma unroll 8
        for (int j=lane; j<H_; j+=32) s += t[j]*wr[j];
        #pragma unroll
        for (int o=16;o>0;o>>=1) s += __shfl_xor_sync(0xffffffffu, s, o);
        if (lane==0) g_orig[b*C_+c] = s + ob[c];
    }
}

// ---------------- 6) expert GEMM1 + LN + GELU, 3xTF32 ------------------------
// block 64(gathered rows) x 256, 8 warps (1x8), warp 64x32, BK=32, K=1024
__global__ void __launch_bounds__(256) egemm1_kernel(const float* __restrict__ eW1,
                                                     const float* __restrict__ eb1,
                                                     const float* __restrict__ eg,
                                                     const float* __restrict__ ebt){
    extern __shared__ float sm[];
    float* AsH = sm;
    float* AsL = AsH + 64*36;
    float* BsH = AsL + 64*36;
    float* BsL = BsH + 256*36;
    float* Cs  = sm;                    // reused after mainloop, stride 260
    __shared__ int toks[64];
    int e = blockIdx.y;
    int n = g_cnt[e];
    int r0 = blockIdx.x*64;
    if (r0 >= n) return;
    int t = threadIdx.x, lane = t & 31, warp = t >> 5;
    if (t < 64) toks[t] = g_tok[e*B_ + min(r0 + t, n-1)];
    __syncthreads();
    int lr = t >> 3, lc = (t & 7)*4;
    float acc[4][4][4];
    #pragma unroll
    for (int i=0;i<4;i++)
        #pragma unroll
        for (int j=0;j<4;j++)
            #pragma unroll
            for (int k=0;k<4;k++) acc[i][j][k]=0.f;

    const float* wbase = eW1 + (size_t)e*HE_*H_;
    float4 avA[2], avB[8];
    #pragma unroll
    for (int i=0;i<2;i++)
        avA[i] = *(const float4*)(g_pooled + (size_t)toks[lr+32*i]*H_ + lc);
    #pragma unroll
    for (int i=0;i<8;i++)
        avB[i] = *(const float4*)(wbase + (size_t)(lr+32*i)*H_ + lc);

    for (int it=0; it<32; it++){
        #pragma unroll
        for (int i=0;i<2;i++){
            float4 h,l; split4(avA[i], h, l);
            *(float4*)(AsH + (lr+32*i)*36 + lc) = h;
            *(float4*)(AsL + (lr+32*i)*36 + lc) = l;
        }
        #pragma unroll
        for (int i=0;i<8;i++){
            float4 h,l; split4(avB[i], h, l);
            *(float4*)(BsH + (lr+32*i)*36 + lc) = h;
            *(float4*)(BsL + (lr+32*i)*36 + lc) = l;
        }
        __syncthreads();
        if (it+1 < 32){
            int k0 = (it+1)*32;
            #pragma unroll
            for (int i=0;i<2;i++)
                avA[i] = *(const float4*)(g_pooled + (size_t)toks[lr+32*i]*H_ + k0 + lc);
            #pragma unroll
            for (int i=0;i<8;i++)
                avB[i] = *(const float4*)(wbase + (size_t)(lr+32*i)*H_ + k0 + lc);
        }
        compute_k32(AsH, AsL, BsH, BsL, 0, warp*32, lane, acc);
        __syncthreads();
    }
    // stash C tile in smem (overwrites As/Bs)
    int g = lane>>2, q = lane&3;
    #pragma unroll
    for (int nf=0;nf<4;nf++){
        int col = warp*32 + nf*8 + 2*q;
        #pragma unroll
        for (int mf=0;mf<4;mf++){
            int row = mf*16 + g;
            float2 a; a.x=acc[mf][nf][0]; a.y=acc[mf][nf][1];
            float2 b; b.x=acc[mf][nf][2]; b.y=acc[mf][nf][3];
            *(float2*)&Cs[row*260 + col]     = a;
            *(float2*)&Cs[(row+8)*260 + col] = b;
        }
    }
    __syncthreads();
    // LN + GELU epilogue: 4 threads per row, 64 cols each
    int j = t & 3, row = t >> 2;
    int gr = r0 + row;
    const float* b1 = eb1 + e*HE_;
    float s = 0.f, qs = 0.f;
    #pragma unroll
    for (int cc=0; cc<64; cc+=4){
        float4 v = *(float4*)&Cs[row*260 + j*64 + cc];
        float4 bb = *(const float4*)&b1[j*64 + cc];
        v.x+=bb.x; v.y+=bb.y; v.z+=bb.z; v.w+=bb.w;
        s  += v.x+v.y+v.z+v.w;
        qs += v.x*v.x+v.y*v.y+v.z*v.z+v.w*v.w;
    }
    s  += __shfl_xor_sync(0xffffffffu, s, 1);  s  += __shfl_xor_sync(0xffffffffu, s, 2);
    qs += __shfl_xor_sync(0xffffffffu, qs, 1); qs += __shfl_xor_sync(0xffffffffu, qs, 2);
    float m = s*(1.f/HE_);
    float var = qs*(1.f/HE_) - m*m;
    float rstd = rsqrtf(var + 1e-5f);
    if (gr < n){
        float* outp = g_h + ((size_t)e*B_ + gr)*HE_ + j*64;
        const float* gp = eg  + e*HE_ + j*64;
        const float* bp = ebt + e*HE_ + j*64;
        #pragma unroll
        for (int cc=0; cc<64; cc+=4){
            float4 v = *(float4*)&Cs[row*260 + j*64 + cc];
            float4 bb = *(const float4*)&b1[j*64 + cc];
            float4 gg = *(const float4*)&gp[cc];
            float4 bt = *(const float4*)&bp[cc];
            float z0 = (v.x+bb.x-m)*rstd*gg.x + bt.x;
            float z1 = (v.y+bb.y-m)*rstd*gg.y + bt.y;
            float z2 = (v.z+bb.z-m)*rstd*gg.z + bt.z;
            float z3 = (v.w+bb.w-m)*rstd*gg.w + bt.w;
            float4 o;
            o.x = 0.5f*z0*(1.f+erff(z0*0.70710678118654752f));
            o.y = 0.5f*z1*(1.f+erff(z1*0.70710678118654752f));
            o.z = 0.5f*z2*(1.f+erff(z2*0.70710678118654752f));
            o.w = 0.5f*z3*(1.f+erff(z3*0.70710678118654752f));
            *(float4*)&outp[cc] = o;
        }
    }
}

// ---------------- 7) expert GEMM2 + fused proj, 3xTF32 -----------------------
// block 64x256, K=256 (8 iters)
__global__ void __launch_bounds__(256) egemm2_kernel(const float* __restrict__ eW2,
                                                     const float* __restrict__ eb2,
                                                     const float* __restrict__ pW,
                                                     const float* __restrict__ pb){
    extern __shared__ float sm[];
    float* AsH = sm;
    float* AsL = AsH + 64*36;
    float* BsH = AsL + 64*36;
    float* BsL = BsH + 256*36;
    float* Cs  = sm;
    __shared__ int toks[64], slots[64];
    int e = blockIdx.y;
    int n = g_cnt[e];
    int r0 = blockIdx.x*64;
    if (r0 >= n) return;
    int t = threadIdx.x, lane = t & 31, warp = t >> 5;
    if (t < 64){
        int rc = min(r0 + t, n-1);
        toks[t]  = g_tok [e*B_+rc];
        slots[t] = g_slot[e*B_+rc];
    }
    __syncthreads();
    int lr = t >> 3, lc = (t & 7)*4;
    float acc[4][4][4];
    #pragma unroll
    for (int i=0;i<4;i++)
        #pragma unroll
        for (int j=0;j<4;j++)
            #pragma unroll
            for (int k=0;k<4;k++) acc[i][j][k]=0.f;

    const float* wbase = eW2 + (size_t)e*HE_*HE_;
    const float* abase = g_h + (size_t)e*B_*HE_;
    int ar0 = min(r0 + lr,      n-1);
    int ar1 = min(r0 + lr + 32, n-1);
    float4 avA[2], avB[8];
    avA[0] = *(const float4*)(abase + (size_t)ar0*HE_ + lc);
    avA[1] = *(const float4*)(abase + (size_t)ar1*HE_ + lc);
    #pragma unroll
    for (int i=0;i<8;i++)
        avB[i] = *(const float4*)(wbase + (size_t)(lr+32*i)*HE_ + lc);

    for (int it=0; it<8; it++){
        {
            float4 h,l;
            split4(avA[0], h, l);
            *(float4*)(AsH + lr*36 + lc) = h;
            *(float4*)(AsL + lr*36 + lc) = l;
            split4(avA[1], h, l);
            *(float4*)(AsH + (lr+32)*36 + lc) = h;
            *(float4*)(AsL + (lr+32)*36 + lc) = l;
        }
        #pragma unroll
        for (int i=0;i<8;i++){
            float4 h,l; split4(avB[i], h, l);
            *(float4*)(BsH + (lr+32*i)*36 + lc) = h;
            *(float4*)(BsL + (lr+32*i)*36 + lc) = l;
        }
        __syncthreads();
        if (it+1 < 8){
            int k0 = (it+1)*32;
            avA[0] = *(const float4*)(abase + (size_t)ar0*HE_ + k0 + lc);
            avA[1] = *(const float4*)(abase + (size_t)ar1*HE_ + k0 + lc);
            #pragma unroll
            for (int i=0;i<8;i++)
                avB[i] = *(const float4*)(wbase + (size_t)(lr+32*i)*HE_ + k0 + lc);
        }
        compute_k32(AsH, AsL, BsH, BsL, 0, warp*32, lane, acc);
        __syncthreads();
    }
    int g = lane>>2, q = lane&3;
    #pragma unroll
    for (int nf=0;nf<4;nf++){
        int col = warp*32 + nf*8 + 2*q;
        #pragma unroll
        for (int mf=0;mf<4;mf++){
            int row = mf*16 + g;
            float2 a; a.x=acc[mf][nf][0]; a.y=acc[mf][nf][1];
            float2 b; b.x=acc[mf][nf][2]; b.y=acc[mf][nf][3];
            *(float2*)&Cs[row*260 + col]     = a;
            *(float2*)&Cs[(row+8)*260 + col] = b;
        }
    }
    __syncthreads();
    // proj epilogue: 4 threads/row, project 256 -> C=3
    int j = t & 3, row = t >> 2;
    int gr = r0 + row;
    const float* b2 = eb2 + e*HE_;
    float p0=0.f, p1=0.f, p2=0.f;
    #pragma unroll
    for (int cc=0; cc<64; cc+=4){
        float4 v = *(float4*)&Cs[row*260 + j*64 + cc];
        float4 bb = *(const float4*)&b2[j*64 + cc];
        v.x+=bb.x; v.y+=bb.y; v.z+=bb.z; v.w+=bb.w;
        float4 w0 = *(const float4*)&pW[0*HE_ + j*64 + cc];
        float4 w1 = *(const float4*)&pW[1*HE_ + j*64 + cc];
        float4 w2 = *(const float4*)&pW[2*HE_ + j*64 + cc];
        p0 += v.x*w0.x + v.y*w0.y + v.z*w0.z + v.w*w0.w;
        p1 += v.x*w1.x + v.y*w1.y + v.z*w1.z + v.w*w1.w;
        p2 += v.x*w2.x + v.y*w2.y + v.z*w2.z + v.w*w2.w;
    }
    p0 += __shfl_xor_sync(0xffffffffu, p0, 1); p0 += __shfl_xor_sync(0xffffffffu, p0, 2);
    p1 += __shfl_xor_sync(0xffffffffu, p1, 1); p1 += __shfl_xor_sync(0xffffffffu, p1, 2);
    p2 += __shfl_xor_sync(0xffffffffu, p2, 1); p2 += __shfl_xor_sync(0xffffffffu, p2, 2);
    if (j == 0 && gr < n){
        int b = toks[row], sl = slots[row];
        float* o = &g_el[(b*K_+sl)*C_];
        o[0] = p0 + pb[0];
        o[1] = p1 + pb[1];
        o[2] = p2 + pb[2];
    }
}

// ---------------- 8) final head ---------------------------------------------
__global__ void __launch_bounds__(256) final_kernel(const float* __restrict__ f1W,
                                                    const float* __restrict__ f1b,
                                                    const float* __restrict__ fg,
                                                    const float* __restrict__ fbt,
                                                    const float* __restrict__ f2W,
                                                    const float* __restrict__ f2b,
                                                    float* __restrict__ out){
    int b = blockIdx.x*blockDim.x + threadIdx.x;
    if (b >= B_) return;
    float comb[2*C_];
    #pragma unroll
    for (int c=0;c<C_;c++) comb[c] = g_orig[b*C_+c];
    float moe[C_]={0.f,0.f,0.f};
    #pragma unroll
    for (int k=0;k<K_;k++){
        float w = g_topw[b*K_+k];
        const float* el = &g_el[(b*K_+k)*C_];
        #pragma unroll
        for (int c=0;c<C_;c++) moe[c] += w*el[c];
    }
    #pragma unroll
    for (int c=0;c<C_;c++) comb[C_+c]=moe[c];
    float y[C_];
    #pragma unroll
    for (int c=0;c<C_;c++){
        float s = f1b[c];
        #pragma unroll
        for (int jj=0;jj<2*C_;jj++) s += comb[jj]*f1W[c*(2*C_)+jj];
        y[c]=s;
    }
    float m = (y[0]+y[1]+y[2])*(1.f/3.f);
    float d0=y[0]-m, d1=y[1]-m, d2=y[2]-m;
    float var = (d0*d0+d1*d1+d2*d2)*(1.f/3.f);
    float rs = rsqrtf(var + 1e-5f);
    float z[C_];
    #pragma unroll
    for (int c=0;c<C_;c++) z[c] = fmaxf(0.f, (y[c]-m)*rs*fg[c] + fbt[c]);
    #pragma unroll
    for (int c2=0;c2<C_;c2++){
        float s = f2b[c2];
        #pragma unroll
        for (int c=0;c<C_;c++) s += z[c]*f2W[c2*C_+c];
        out[b*C_+c2] = s;
    }
}

// ---------------- streams/events (host-side objects, created once) -----------
struct SideStreams {
    cudaStream_t sB, sC;
    cudaEvent_t  evFork, evJB, evJC;
    SideStreams(){
        cudaStreamCreateWithFlags(&sB, cudaStreamNonBlocking);
        cudaStreamCreateWithFlags(&sC, cudaStreamNonBlocking);
        cudaEventCreateWithFlags(&evFork, cudaEventDisableTiming);
        cudaEventCreateWithFlags(&evJB,   cudaEventDisableTiming);
        cudaEventCreateWithFlags(&evJC,   cudaEventDisableTiming);
    }
};
static SideStreams g_ss;

// ---------------- launch -----------------------------------------------------
extern "C" void kernel_launch(void* const* d_in, const int* in_sizes, int n_in,
                              void* d_out, int out_size){
    const float* hid = (const float*)d_in[0];
    const float* rW  = (const float*)d_in[1];
    const float* rb  = (const float*)d_in[2];
    const float* eW1 = (const float*)d_in[3];
    const float* eb1 = (const float*)d_in[4];
    const float* eg  = (const float*)d_in[5];
    const float* ebt = (const float*)d_in[6];
    const float* eW2 = (const float*)d_in[7];
    const float* eb2 = (const float*)d_in[8];
    const float* pW  = (const float*)d_in[9];
    const float* pb  = (const float*)d_in[10];
    const float* dW  = (const float*)d_in[11];
    const float* db  = (const float*)d_in[12];
    const float* oW  = (const float*)d_in[13];
    const float* ob  = (const float*)d_in[14];
    const float* f1W = (const float*)d_in[15];
    const float* f1b = (const float*)d_in[16];
    const float* fg  = (const float*)d_in[17];
    const float* fbt = (const float*)d_in[18];
    const float* f2W = (const float*)d_in[19];
    const float* f2b = (const float*)d_in[20];
    float* out = (float*)d_out;

    const int DSM_DENSE = 4*128*36*4;             // 73728 B
    const int DSM_EG    = (2*64*36 + 2*256*36)*4; // 92160 B
    cudaFuncSetAttribute(dense_tanh_kernel, cudaFuncAttributeMaxDynamicSharedMemorySize, DSM_DENSE);
    cudaFuncSetAttribute(egemm1_kernel,     cudaFuncAttributeMaxDynamicSharedMemorySize, DSM_EG);
    cudaFuncSetAttribute(egemm2_kernel,     cudaFuncAttributeMaxDynamicSharedMemorySize, DSM_EG);

    // fork: branches B (router->gather) and C (dense->orig) off the main stream
    cudaEventRecord(g_ss.evFork, 0);
    cudaStreamWaitEvent(g_ss.sB, g_ss.evFork, 0);
    cudaStreamWaitEvent(g_ss.sC, g_ss.evFork, 0);

    // main stream: the HBM-bound pool (critical path)
    pool_kernel<<<B_, 256>>>(hid);

    // branch B: router + gather (producers of g_topi/g_topw/g_cnt/g_tok/g_slot)
    router_topk_kernel<<<B_, 512, 0, g_ss.sB>>>(hid, rW, rb);
    gather_kernel<<<1, 1024, 0, g_ss.sB>>>();
    cudaEventRecord(g_ss.evJB, g_ss.sB);

    // branch C: dense head + orig (producers of g_orig)
    dense_tanh_kernel<<<dim3(8,8), 256, DSM_DENSE, g_ss.sC>>>(hid, dW, db);
    orig_kernel<<<B_/8, 256, 0, g_ss.sC>>>(oW, ob);
    cudaEventRecord(g_ss.evJC, g_ss.sC);

    // join B before expert GEMMs (need gather results); pool ordering is implicit (same stream)
    cudaStreamWaitEvent(0, g_ss.evJB, 0);
    egemm1_kernel<<<dim3(B_/64, E_), 256, DSM_EG>>>(eW1, eb1, eg, ebt);
    egemm2_kernel<<<dim3(B_/64, E_), 256, DSM_EG>>>(eW2, eb2, pW, pb);

    // join C before final head (needs g_orig)
    cudaStreamWaitEvent(0, g_ss.evJC, 0);
    final_kernel<<<B_/256, 256>>>(f1W, f1b, fg, fbt, f2W, f2b, out);
}

// round 6
// speedup vs baseline: 1.5972x; 1.1715x over previous
#include <cuda_runtime.h>
#include <math.h>
#include <stdint.h>

#define B_  1024
#define S_  256
#define H_  1024
#define E_  16
#define K_  4
#define HE_ 256
#define C_  3

// ---------------- device scratch ---------------------------------------------
__device__ float g_pooled[B_*H_];
__device__ float g_t[B_*H_];
__device__ float g_orig[B_*C_];
__device__ int   g_topi[B_*K_];
__device__ float g_topw[B_*K_];
__device__ int   g_cnt[E_];
__device__ int   g_tok[E_*B_];
__device__ int   g_slot[E_*B_];
__device__ float g_h[(size_t)E_*B_*HE_];
__device__ float g_el[B_*K_*C_];

// ---------------- cp.async helpers -------------------------------------------
__device__ __forceinline__ void cp16(void* dst, const void* src){
    unsigned d = (unsigned)__cvta_generic_to_shared(dst);
    asm volatile("cp.async.cg.shared.global [%0], [%1], 16;\n" :: "r"(d), "l"(src));
}
__device__ __forceinline__ void cp_commit(){ asm volatile("cp.async.commit_group;\n" ::); }
__device__ __forceinline__ void cp_wait1(){ asm volatile("cp.async.wait_group 1;\n" ::); }
__device__ __forceinline__ void cp_wait0(){ asm volatile("cp.async.wait_group 0;\n" ::); }

// ---------------- tf32 mma + in-register split -------------------------------
__device__ __forceinline__ void mma_tf32(float* c, const unsigned* a, const unsigned* b){
    asm volatile("mma.sync.aligned.m16n8k8.row.col.f32.tf32.tf32.f32 "
        "{%0,%1,%2,%3},{%4,%5,%6,%7},{%8,%9},{%0,%1,%2,%3};\n"
        : "+f"(c[0]), "+f"(c[1]), "+f"(c[2]), "+f"(c[3])
        : "r"(a[0]), "r"(a[1]), "r"(a[2]), "r"(a[3]), "r"(b[0]), "r"(b[1]));
}

__device__ __forceinline__ void splitf(float a, unsigned& hi, unsigned& lo){
    unsigned u = __float_as_uint(a) & 0xffffe000u;
    hi = u;
    lo = __float_as_uint(a - __uint_as_float(u));
}

// warp tile 32(m) x 32(n), BK=32, raw fp32 tiles in smem (stride 36), 3xTF32.
__device__ __forceinline__ void compute_raw(const float* __restrict__ As,
                                            const float* __restrict__ Bs,
                                            int wmBase, int wnBase, int lane,
                                            float (&acc)[2][4][4]){
    int g = lane >> 2, q = lane & 3;
    #pragma unroll
    for (int kk = 0; kk < 32; kk += 8){
        unsigned ah[2][4], al[2][4], bh[4][2], bl[4][2];
        #pragma unroll
        for (int mf = 0; mf < 2; mf++){
            int r = wmBase + mf*16 + g;
            const float* p = As + r*36 + kk + q;
            splitf(p[0],      ah[mf][0], al[mf][0]);
            splitf(p[8*36],   ah[mf][1], al[mf][1]);
            splitf(p[4],      ah[mf][2], al[mf][2]);
            splitf(p[8*36+4], ah[mf][3], al[mf][3]);
        }
        #pragma unroll
        for (int nf = 0; nf < 4; nf++){
            int nn = wnBase + nf*8 + g;
            const float* p = Bs + nn*36 + kk + q;
            splitf(p[0], bh[nf][0], bl[nf][0]);
            splitf(p[4], bh[nf][1], bl[nf][1]);
        }
        #pragma unroll
        for (int mf = 0; mf < 2; mf++)
            #pragma unroll
            for (int nf = 0; nf < 4; nf++){
                mma_tf32(acc[mf][nf], ah[mf], bh[nf]);
                mma_tf32(acc[mf][nf], ah[mf], bl[nf]);
                mma_tf32(acc[mf][nf], al[mf], bh[nf]);
            }
    }
}

// ---------------- 1) pooled mean ---------------------------------------------
__global__ void __launch_bounds__(256) pool_kernel(const float* __restrict__ hid){
    int b = blockIdx.x;
    const float4* p = reinterpret_cast<const float4*>(hid + (size_t)b*S_*H_) + threadIdx.x;
    float ax=0.f,ay=0.f,az=0.f,aw=0.f;
    float bx=0.f,by=0.f,bz=0.f,bw=0.f;
    #pragma unroll 4
    for (int s=0; s<S_; s+=2){
        float4 v0 = p[(size_t)s*(H_/4)];
        float4 v1 = p[(size_t)(s+1)*(H_/4)];
        ax+=v0.x; ay+=v0.y; az+=v0.z; aw+=v0.w;
        bx+=v1.x; by+=v1.y; bz+=v1.z; bw+=v1.w;
    }
    float4 r;
    r.x=(ax+bx)*(1.f/S_); r.y=(ay+by)*(1.f/S_);
    r.z=(az+bz)*(1.f/S_); r.w=(aw+bw)*(1.f/S_);
    reinterpret_cast<float4*>(g_pooled + (size_t)b*H_)[threadIdx.x] = r;
}

// ---------------- 2) router + top-4 + softmax --------------------------------
__global__ void __launch_bounds__(512) router_topk_kernel(const float* __restrict__ hid,
                                                          const float* __restrict__ rW,
                                                          const float* __restrict__ rb){
    __shared__ float cls[H_];
    __shared__ float lg[E_];
    int b = blockIdx.x, tid = threadIdx.x;
    cls[tid]       = hid[(size_t)b*S_*H_ + tid];
    cls[tid + 512] = hid[(size_t)b*S_*H_ + tid + 512];
    __syncthreads();
    int w = tid >> 5, lane = tid & 31;
    float s = 0.f;
    const float* wr = rW + w*H_;
    #pragma unroll 8
    for (int j=lane; j<H_; j+=32) s += cls[j]*wr[j];
    #pragma unroll
    for (int o=16;o>0;o>>=1) s += __shfl_xor_sync(0xffffffffu, s, o);
    if (lane==0) lg[w] = s + rb[w];
    __syncthreads();
    if (tid==0){
        float v[E_];
        #pragma unroll
        for (int i=0;i<E_;i++) v[i]=lg[i];
        int   idxs[K_]; float vals[K_];
        for (int k=0;k<K_;k++){
            int bi=0; float bv=-3.0e38f;
            #pragma unroll
            for (int i=0;i<E_;i++){ if (v[i]>bv){ bv=v[i]; bi=i; } }
            idxs[k]=bi; vals[k]=bv; v[bi]=-3.0e38f;
        }
        float m = vals[0], ssum=0.f, wv[K_];
        for (int k=0;k<K_;k++){ wv[k]=expf(vals[k]-m); ssum+=wv[k]; }
        float inv = 1.f/ssum;
        for (int k=0;k<K_;k++){ g_topi[b*K_+k]=idxs[k]; g_topw[b*K_+k]=wv[k]*inv; }
    }
}

// ---------------- 3) gather (single block, smem counters) --------------------
__global__ void __launch_bounds__(1024) gather_kernel(){
    __shared__ int cnt[E_];
    int t = threadIdx.x;
    if (t < E_) cnt[t] = 0;
    __syncthreads();
    #pragma unroll
    for (int i=0;i<4;i++){
        int idx = t + i*1024;
        int e = g_topi[idx];
        int pos = atomicAdd(&cnt[e], 1);
        g_tok [e*B_+pos] = idx >> 2;
        g_slot[e*B_+pos] = idx & 3;
    }
    __syncthreads();
    if (t < E_) g_cnt[t] = cnt[t];
}

// ---------------- 4) dense head: t = tanh(cls @ dW^T + db) -------------------
// 64x64 tile, 128 threads (4 warps 2x2), warp 32x32, BK=32, cp.async 2-stage
__global__ void __launch_bounds__(128) dense_tanh_kernel(const float* __restrict__ hid,
                                                         const float* __restrict__ W,
                                                         const float* __restrict__ bias){
    __shared__ float As[2][64*36];
    __shared__ float Bs[2][64*36];
    int t = threadIdx.x, lane = t & 31, warp = t >> 5;
    int wm = warp >> 1, wn = warp & 1;
    int m0 = blockIdx.y*64, n0 = blockIdx.x*64;
    int lr = t >> 3, lc = (t & 7)*4;
    float acc[2][4][4];
    #pragma unroll
    for (int i=0;i<2;i++)
        #pragma unroll
        for (int j=0;j<4;j++)
            #pragma unroll
            for (int k=0;k<4;k++) acc[i][j][k]=0.f;

    auto load = [&](int s, int k0){
        #pragma unroll
        for (int i=0;i<4;i++){
            int row = lr + 16*i;
            cp16(&As[s][row*36+lc], hid + (size_t)(m0+row)*S_*H_ + k0 + lc);
            cp16(&Bs[s][row*36+lc], W   + (size_t)(n0+row)*H_   + k0 + lc);
        }
    };
    load(0, 0); cp_commit();
    for (int it=0; it<32; it++){
        if (it+1 < 32){ load((it+1)&1, (it+1)*32); cp_commit(); cp_wait1(); }
        else cp_wait0();
        __syncthreads();
        compute_raw(As[it&1], Bs[it&1], wm*32, wn*32, lane, acc);
        __syncthreads();
    }
    int g = lane>>2, q = lane&3;
    #pragma unroll
    for (int nf=0;nf<4;nf++){
        int col = n0 + wn*32 + nf*8 + 2*q;
        float2 bb = *(const float2*)&bias[col];
        #pragma unroll
        for (int mf=0;mf<2;mf++){
            int row = m0 + wm*32 + mf*16 + g;
            float2 o0, o1;
            o0.x = tanhf(acc[mf][nf][0]+bb.x); o0.y = tanhf(acc[mf][nf][1]+bb.y);
            o1.x = tanhf(acc[mf][nf][2]+bb.x); o1.y = tanhf(acc[mf][nf][3]+bb.y);
            *(float2*)&g_t[(size_t)row*H_ + col]     = o0;
            *(float2*)&g_t[(size_t)(row+8)*H_ + col] = o1;
        }
    }
}

// ---------------- 5) orig = t @ out_W^T + out_b ------------------------------
__global__ void __launch_bounds__(256) orig_kernel(const float* __restrict__ oW,
                                                   const float* __restrict__ ob){
    int w = threadIdx.x >> 5, lane = threadIdx.x & 31;
    int b = blockIdx.x*8 + w;
    const float* t = g_t + (size_t)b*H_;
    for (int c=0;c<C_;c++){
        float s=0.f;
        const float* wr = oW + c*H_;
        #pragma unroll 8
        for (int j=lane; j<H_; j+=32) s += t[j]*wr[j];
        #pragma unroll
        for (int o=16;o>0;o>>=1) s += __shfl_xor_sync(0xffffffffu, s, o);
        if (lane==0) g_orig[b*C_+c] = s + ob[c];
    }
}

// ---------------- 6) expert GEMM1 + LN + GELU --------------------------------
// 32(rows) x 256(cols) tile, 256 threads (8 warps, warp 32x32), BK=32, K=1024
__global__ void __launch_bounds__(256) egemm1_kernel(const float* __restrict__ eW1,
                                                     const float* __restrict__ eb1,
                                                     const float* __restrict__ eg,
                                                     const float* __restrict__ ebt){
    extern __shared__ float sm[];
    float* As0 = sm;                 // 32*36
    float* As1 = sm + 32*36;
    float* Bs0 = sm + 2*32*36;       // 256*36
    float* Bs1 = sm + 2*32*36 + 256*36;
    float* Cs  = sm;                 // overlay after mainloop, stride 260
    __shared__ int toks[32];
    int e = blockIdx.y;
    int n = g_cnt[e];
    int r0 = blockIdx.x*32;
    if (r0 >= n) return;
    int t = threadIdx.x, lane = t & 31, warp = t >> 5;
    if (t < 32) toks[t] = g_tok[e*B_ + min(r0 + t, n-1)];
    __syncthreads();
    int lr = t >> 3, lc = (t & 7)*4;
    float acc[2][4][4];
    #pragma unroll
    for (int i=0;i<2;i++)
        #pragma unroll
        for (int j=0;j<4;j++)
            #pragma unroll
            for (int k=0;k<4;k++) acc[i][j][k]=0.f;

    const float* wbase = eW1 + (size_t)e*HE_*H_;
    const float* arow = g_pooled + (size_t)toks[lr]*H_ + lc;
    auto load = [&](float* Asb, float* Bsb, int k0){
        cp16(&Asb[lr*36+lc], arow + k0);
        #pragma unroll
        for (int i=0;i<8;i++){
            int row = lr + 32*i;
            cp16(&Bsb[row*36+lc], wbase + (size_t)row*H_ + k0 + lc);
        }
    };
    load(As0, Bs0, 0); cp_commit();
    for (int it=0; it<32; it++){
        if (it+1 < 32){
            if ((it+1)&1) load(As1, Bs1, (it+1)*32); else load(As0, Bs0, (it+1)*32);
            cp_commit(); cp_wait1();
        } else cp_wait0();
        __syncthreads();
        if (it&1) compute_raw(As1, Bs1, 0, warp*32, lane, acc);
        else      compute_raw(As0, Bs0, 0, warp*32, lane, acc);
        __syncthreads();
    }
    // stage C tile (32 x 256) into smem
    int g = lane>>2, q = lane&3;
    #pragma unroll
    for (int nf=0;nf<4;nf++){
        int col = warp*32 + nf*8 + 2*q;
        #pragma unroll
        for (int mf=0;mf<2;mf++){
            int row = mf*16 + g;
            float2 a; a.x=acc[mf][nf][0]; a.y=acc[mf][nf][1];
            float2 b; b.x=acc[mf][nf][2]; b.y=acc[mf][nf][3];
            *(float2*)&Cs[row*260 + col]     = a;
            *(float2*)&Cs[(row+8)*260 + col] = b;
        }
    }
    __syncthreads();
    // LN + GELU: 8 threads per row, 32 cols each
    int j = t & 7, row = t >> 3;
    int gr = r0 + row;
    const float* b1 = eb1 + e*HE_;
    float s = 0.f, qs = 0.f;
    #pragma unroll
    for (int cc=0; cc<32; cc+=4){
        float4 v = *(float4*)&Cs[row*260 + j*32 + cc];
        float4 bb = *(const float4*)&b1[j*32 + cc];
        v.x+=bb.x; v.y+=bb.y; v.z+=bb.z; v.w+=bb.w;
        s  += v.x+v.y+v.z+v.w;
        qs += v.x*v.x+v.y*v.y+v.z*v.z+v.w*v.w;
    }
    s  += __shfl_xor_sync(0xffffffffu, s, 1);  s  += __shfl_xor_sync(0xffffffffu, s, 2);  s  += __shfl_xor_sync(0xffffffffu, s, 4);
    qs += __shfl_xor_sync(0xffffffffu, qs, 1); qs += __shfl_xor_sync(0xffffffffu, qs, 2); qs += __shfl_xor_sync(0xffffffffu, qs, 4);
    float m = s*(1.f/HE_);
    float var = qs*(1.f/HE_) - m*m;
    float rstd = rsqrtf(var + 1e-5f);
    if (gr < n){
        float* outp = g_h + ((size_t)e*B_ + gr)*HE_ + j*32;
        const float* gp = eg  + e*HE_ + j*32;
        const float* bp = ebt + e*HE_ + j*32;
        #pragma unroll
        for (int cc=0; cc<32; cc+=4){
            float4 v = *(float4*)&Cs[row*260 + j*32 + cc];
            float4 bb = *(const float4*)&b1[j*32 + cc];
            float4 gg = *(const float4*)&gp[cc];
            float4 bt = *(const float4*)&bp[cc];
            float z0 = (v.x+bb.x-m)*rstd*gg.x + bt.x;
            float z1 = (v.y+bb.y-m)*rstd*gg.y + bt.y;
            float z2 = (v.z+bb.z-m)*rstd*gg.z + bt.z;
            float z3 = (v.w+bb.w-m)*rstd*gg.w + bt.w;
            float4 o;
            o.x = 0.5f*z0*(1.f+erff(z0*0.70710678118654752f));
            o.y = 0.5f*z1*(1.f+erff(z1*0.70710678118654752f));
            o.z = 0.5f*z2*(1.f+erff(z2*0.70710678118654752f));
            o.w = 0.5f*z3*(1.f+erff(z3*0.70710678118654752f));
            *(float4*)&outp[cc] = o;
        }
    }
}

// ---------------- 7) expert GEMM2 + fused proj -------------------------------
// 32 x 256 tile, K=256 (8 iters)
__global__ void __launch_bounds__(256) egemm2_kernel(const float* __restrict__ eW2,
                                                     const float* __restrict__ eb2,
                                                     const float* __restrict__ pW,
                                                     const float* __restrict__ pb){
    extern __shared__ float sm[];
    float* As0 = sm;
    float* As1 = sm + 32*36;
    float* Bs0 = sm + 2*32*36;
    float* Bs1 = sm + 2*32*36 + 256*36;
    float* Cs  = sm;
    int e = blockIdx.y;
    int n = g_cnt[e];
    int r0 = blockIdx.x*32;
    if (r0 >= n) return;
    int t = threadIdx.x, lane = t & 31, warp = t >> 5;
    int lr = t >> 3, lc = (t & 7)*4;
    float acc[2][4][4];
    #pragma unroll
    for (int i=0;i<2;i++)
        #pragma unroll
        for (int j=0;j<4;j++)
            #pragma unroll
            for (int k=0;k<4;k++) acc[i][j][k]=0.f;

    const float* wbase = eW2 + (size_t)e*HE_*HE_;
    const float* arow = g_h + ((size_t)e*B_ + min(r0 + lr, n-1))*HE_ + lc;
    auto load = [&](float* Asb, float* Bsb, int k0){
        cp16(&Asb[lr*36+lc], arow + k0);
        #pragma unroll
        for (int i=0;i<8;i++){
            int row = lr + 32*i;
            cp16(&Bsb[row*36+lc], wbase + (size_t)row*HE_ + k0 + lc);
        }
    };
    load(As0, Bs0, 0); cp_commit();
    for (int it=0; it<8; it++){
        if (it+1 < 8){
            if ((it+1)&1) load(As1, Bs1, (it+1)*32); else load(As0, Bs0, (it+1)*32);
            cp_commit(); cp_wait1();
        } else cp_wait0();
        __syncthreads();
        if (it&1) compute_raw(As1, Bs1, 0, warp*32, lane, acc);
        else      compute_raw(As0, Bs0, 0, warp*32, lane, acc);
        __syncthreads();
    }
    int g = lane>>2, q = lane&3;
    #pragma unroll
    for (int nf=0;nf<4;nf++){
        int col = warp*32 + nf*8 + 2*q;
        #pragma unroll
        for (int mf=0;mf<2;mf++){
            int row = mf*16 + g;
            float2 a; a.x=acc[mf][nf][0]; a.y=acc[mf][nf][1];
            float2 b; b.x=acc[mf][nf][2]; b.y=acc[mf][nf][3];
            *(float2*)&Cs[row*260 + col]     = a;
            *(float2*)&Cs[(row+8)*260 + col] = b;
        }
    }
    __syncthreads();
    // proj epilogue: 8 threads/row, 32 cols each -> C=3
    int j = t & 7, row = t >> 3;
    int gr = r0 + row;
    const float* b2 = eb2 + e*HE_;
    float p0=0.f, p1=0.f, p2=0.f;
    #pragma unroll
    for (int cc=0; cc<32; cc+=4){
        float4 v = *(float4*)&Cs[row*260 + j*32 + cc];
        float4 bb = *(const float4*)&b2[j*32 + cc];
        v.x+=bb.x; v.y+=bb.y; v.z+=bb.z; v.w+=bb.w;
        float4 w0 = *(const float4*)&pW[0*HE_ + j*32 + cc];
        float4 w1 = *(const float4*)&pW[1*HE_ + j*32 + cc];
        float4 w2 = *(const float4*)&pW[2*HE_ + j*32 + cc];
        p0 += v.x*w0.x + v.y*w0.y + v.z*w0.z + v.w*w0.w;
        p1 += v.x*w1.x + v.y*w1.y + v.z*w1.z + v.w*w1.w;
        p2 += v.x*w2.x + v.y*w2.y + v.z*w2.z + v.w*w2.w;
    }
    p0 += __shfl_xor_sync(0xffffffffu, p0, 1); p0 += __shfl_xor_sync(0xffffffffu, p0, 2); p0 += __shfl_xor_sync(0xffffffffu, p0, 4);
    p1 += __shfl_xor_sync(0xffffffffu, p1, 1); p1 += __shfl_xor_sync(0xffffffffu, p1, 2); p1 += __shfl_xor_sync(0xffffffffu, p1, 4);
    p2 += __shfl_xor_sync(0xffffffffu, p2, 1); p2 += __shfl_xor_sync(0xffffffffu, p2, 2); p2 += __shfl_xor_sync(0xffffffffu, p2, 4);
    if (j == 0 && gr < n){
        int b = g_tok[e*B_+gr], sl = g_slot[e*B_+gr];
        float* o = &g_el[(b*K_+sl)*C_];
        o[0] = p0 + pb[0];
        o[1] = p1 + pb[1];
        o[2] = p2 + pb[2];
    }
}

// ---------------- 8) final head ---------------------------------------------
__global__ void __launch_bounds__(256) final_kernel(const float* __restrict__ f1W,
                                                    const float* __restrict__ f1b,
                                                    const float* __restrict__ fg,
                                                    const float* __restrict__ fbt,
                                                    const float* __restrict__ f2W,
                                                    const float* __restrict__ f2b,
                                                    float* __restrict__ out){
    int b = blockIdx.x*blockDim.x + threadIdx.x;
    if (b >= B_) return;
    float comb[2*C_];
    #pragma unroll
    for (int c=0;c<C_;c++) comb[c] = g_orig[b*C_+c];
    float moe[C_]={0.f,0.f,0.f};
    #pragma unroll
    for (int k=0;k<K_;k++){
        float w = g_topw[b*K_+k];
        const float* el = &g_el[(b*K_+k)*C_];
        #pragma unroll
        for (int c=0;c<C_;c++) moe[c] += w*el[c];
    }
    #pragma unroll
    for (int c=0;c<C_;c++) comb[C_+c]=moe[c];
    float y[C_];
    #pragma unroll
    for (int c=0;c<C_;c++){
        float s = f1b[c];
        #pragma unroll
        for (int jj=0;jj<2*C_;jj++) s += comb[jj]*f1W[c*(2*C_)+jj];
        y[c]=s;
    }
    float m = (y[0]+y[1]+y[2])*(1.f/3.f);
    float d0=y[0]-m, d1=y[1]-m, d2=y[2]-m;
    float var = (d0*d0+d1*d1+d2*d2)*(1.f/3.f);
    float rs = rsqrtf(var + 1e-5f);
    float z[C_];
    #pragma unroll
    for (int c=0;c<C_;c++) z[c] = fmaxf(0.f, (y[c]-m)*rs*fg[c] + fbt[c]);
    #pragma unroll
    for (int c2=0;c2<C_;c2++){
        float s = f2b[c2];
        #pragma unroll
        for (int c=0;c<C_;c++) s += z[c]*f2W[c2*C_+c];
        out[b*C_+c2] = s;
    }
}

// ---------------- streams/events (host-side objects, created once) -----------
struct SideStreams {
    cudaStream_t sB, sC;
    cudaEvent_t  evFork, evJB, evJC;
    SideStreams(){
        cudaStreamCreateWithFlags(&sB, cudaStreamNonBlocking);
        cudaStreamCreateWithFlags(&sC, cudaStreamNonBlocking);
        cudaEventCreateWithFlags(&evFork, cudaEventDisableTiming);
        cudaEventCreateWithFlags(&evJB,   cudaEventDisableTiming);
        cudaEventCreateWithFlags(&evJC,   cudaEventDisableTiming);
    }
};
static SideStreams g_ss;

// ---------------- launch -----------------------------------------------------
extern "C" void kernel_launch(void* const* d_in, const int* in_sizes, int n_in,
                              void* d_out, int out_size){
    const float* hid = (const float*)d_in[0];
    const float* rW  = (const float*)d_in[1];
    const float* rb  = (const float*)d_in[2];
    const float* eW1 = (const float*)d_in[3];
    const float* eb1 = (const float*)d_in[4];
    const float* eg  = (const float*)d_in[5];
    const float* ebt = (const float*)d_in[6];
    const float* eW2 = (const float*)d_in[7];
    const float* eb2 = (const float*)d_in[8];
    const float* pW  = (const float*)d_in[9];
    const float* pb  = (const float*)d_in[10];
    const float* dW  = (const float*)d_in[11];
    const float* db  = (const float*)d_in[12];
    const float* oW  = (const float*)d_in[13];
    const float* ob  = (const float*)d_in[14];
    const float* f1W = (const float*)d_in[15];
    const float* f1b = (const float*)d_in[16];
    const float* fg  = (const float*)d_in[17];
    const float* fbt = (const float*)d_in[18];
    const float* f2W = (const float*)d_in[19];
    const float* f2b = (const float*)d_in[20];
    float* out = (float*)d_out;

    const int DSM_EG = (2*32*36 + 2*256*36)*4;   // 82944 B
    cudaFuncSetAttribute(egemm1_kernel, cudaFuncAttributeMaxDynamicSharedMemorySize, DSM_EG);
    cudaFuncSetAttribute(egemm2_kernel, cudaFuncAttributeMaxDynamicSharedMemorySize, DSM_EG);

    // fork branches
    cudaEventRecord(g_ss.evFork, 0);
    cudaStreamWaitEvent(g_ss.sB, g_ss.evFork, 0);
    cudaStreamWaitEvent(g_ss.sC, g_ss.evFork, 0);

    // main stream: HBM-bound pool (critical path)
    pool_kernel<<<B_, 256>>>(hid);

    // branch B: router + gather
    router_topk_kernel<<<B_, 512, 0, g_ss.sB>>>(hid, rW, rb);
    gather_kernel<<<1, 1024, 0, g_ss.sB>>>();
    cudaEventRecord(g_ss.evJB, g_ss.sB);

    // branch C: dense head + orig
    dense_tanh_kernel<<<dim3(16,16), 128, 0, g_ss.sC>>>(hid, dW, db);
    orig_kernel<<<B_/8, 256, 0, g_ss.sC>>>(oW, ob);
    cudaEventRecord(g_ss.evJC, g_ss.sC);

    // join B before expert GEMMs
    cudaStreamWaitEvent(0, g_ss.evJB, 0);
    egemm1_kernel<<<dim3(B_/32, E_), 256, DSM_EG>>>(eW1, eb1, eg, ebt);
    egemm2_kernel<<<dim3(B_/32, E_), 256, DSM_EG>>>(eW2, eb2, pW, pb);

    // join C before final head
    cudaStreamWaitEvent(0, g_ss.evJC, 0);
    final_kernel<<<B_/256, 256>>>(f1W, f1b, fg, fbt, f2W, f2b, out);
}

// round 7
// speedup vs baseline: 1.7273x; 1.0815x over previous
#include <cuda_runtime.h>
#include <math.h>
#include <stdint.h>

#define B_  1024
#define S_  256
#define H_  1024
#define E_  16
#define K_  4
#define HE_ 256
#define C_  3

// ---------------- device scratch ---------------------------------------------
__device__ float g_pooled[B_*H_];
__device__ float g_t[B_*H_];
__device__ float g_orig[B_*C_];
__device__ int   g_topi[B_*K_];
__device__ float g_topw[B_*K_];
__device__ int   g_cnt[E_];
__device__ int   g_tok[E_*B_];
__device__ int   g_slot[E_*B_];
__device__ float g_el[B_*K_*C_];

// ---------------- cp.async helpers -------------------------------------------
__device__ __forceinline__ void cp16(void* dst, const void* src){
    unsigned d = (unsigned)__cvta_generic_to_shared(dst);
    asm volatile("cp.async.cg.shared.global [%0], [%1], 16;\n" :: "r"(d), "l"(src));
}
__device__ __forceinline__ void cp_commit(){ asm volatile("cp.async.commit_group;\n" ::); }
__device__ __forceinline__ void cp_wait1(){ asm volatile("cp.async.wait_group 1;\n" ::); }
__device__ __forceinline__ void cp_wait0(){ asm volatile("cp.async.wait_group 0;\n" ::); }

// ---------------- tf32 mma + in-register split -------------------------------
__device__ __forceinline__ void mma_tf32(float* c, const unsigned* a, const unsigned* b){
    asm volatile("mma.sync.aligned.m16n8k8.row.col.f32.tf32.tf32.f32 "
        "{%0,%1,%2,%3},{%4,%5,%6,%7},{%8,%9},{%0,%1,%2,%3};\n"
        : "+f"(c[0]), "+f"(c[1]), "+f"(c[2]), "+f"(c[3])
        : "r"(a[0]), "r"(a[1]), "r"(a[2]), "r"(a[3]), "r"(b[0]), "r"(b[1]));
}

__device__ __forceinline__ void splitf(float a, unsigned& hi, unsigned& lo){
    unsigned u = __float_as_uint(a) & 0xffffe000u;
    hi = u;
    lo = __float_as_uint(a - __uint_as_float(u));
}

// warp tile 32(m) x 32(n), BK=32, raw fp32 smem tiles (stride 36), 3xTF32.
__device__ __forceinline__ void compute_raw(const float* __restrict__ As,
                                            const float* __restrict__ Bs,
                                            int wmBase, int wnBase, int lane,
                                            float (&acc)[2][4][4]){
    int g = lane >> 2, q = lane & 3;
    #pragma unroll
    for (int kk = 0; kk < 32; kk += 8){
        unsigned ah[2][4], al[2][4], bh[4][2], bl[4][2];
        #pragma unroll
        for (int mf = 0; mf < 2; mf++){
            int r = wmBase + mf*16 + g;
            const float* p = As + r*36 + kk + q;
            splitf(p[0],      ah[mf][0], al[mf][0]);
            splitf(p[8*36],   ah[mf][1], al[mf][1]);
            splitf(p[4],      ah[mf][2], al[mf][2]);
            splitf(p[8*36+4], ah[mf][3], al[mf][3]);
        }
        #pragma unroll
        for (int nf = 0; nf < 4; nf++){
            int nn = wnBase + nf*8 + g;
            const float* p = Bs + nn*36 + kk + q;
            splitf(p[0], bh[nf][0], bl[nf][0]);
            splitf(p[4], bh[nf][1], bl[nf][1]);
        }
        #pragma unroll
        for (int mf = 0; mf < 2; mf++)
            #pragma unroll
            for (int nf = 0; nf < 4; nf++){
                mma_tf32(acc[mf][nf], ah[mf], bh[nf]);
                mma_tf32(acc[mf][nf], ah[mf], bl[nf]);
                mma_tf32(acc[mf][nf], al[mf], bh[nf]);
            }
    }
}

// warp tile 16(m) x 32(n); A stride templated (36 for staged tile, 260 for Cs).
template<int AS>
__device__ __forceinline__ void compute16(const float* __restrict__ Asl,
                                          const float* __restrict__ Bs,
                                          int wnBase, int lane, float (&acc)[4][4]){
    int g = lane >> 2, q = lane & 3;
    #pragma unroll
    for (int kk = 0; kk < 32; kk += 8){
        unsigned ah[4], al[4], bh[4][2], bl[4][2];
        const float* p = Asl + g*AS + kk + q;
        splitf(p[0],      ah[0], al[0]);
        splitf(p[8*AS],   ah[1], al[1]);
        splitf(p[4],      ah[2], al[2]);
        splitf(p[8*AS+4], ah[3], al[3]);
        #pragma unroll
        for (int nf = 0; nf < 4; nf++){
            const float* pb = Bs + (wnBase + nf*8 + g)*36 + kk + q;
            splitf(pb[0], bh[nf][0], bl[nf][0]);
            splitf(pb[4], bh[nf][1], bl[nf][1]);
        }
        #pragma unroll
        for (int nf = 0; nf < 4; nf++){
            mma_tf32(acc[nf], ah, bh[nf]);
            mma_tf32(acc[nf], ah, bl[nf]);
            mma_tf32(acc[nf], al, bh[nf]);
        }
    }
}

// ---------------- 1) pooled mean ---------------------------------------------
__global__ void __launch_bounds__(256) pool_kernel(const float* __restrict__ hid){
    int b = blockIdx.x;
    const float4* p = reinterpret_cast<const float4*>(hid + (size_t)b*S_*H_) + threadIdx.x;
    float ax=0.f,ay=0.f,az=0.f,aw=0.f;
    float bx=0.f,by=0.f,bz=0.f,bw=0.f;
    #pragma unroll 4
    for (int s=0; s<S_; s+=2){
        float4 v0 = p[(size_t)s*(H_/4)];
        float4 v1 = p[(size_t)(s+1)*(H_/4)];
        ax+=v0.x; ay+=v0.y; az+=v0.z; aw+=v0.w;
        bx+=v1.x; by+=v1.y; bz+=v1.z; bw+=v1.w;
    }
    float4 r;
    r.x=(ax+bx)*(1.f/S_); r.y=(ay+by)*(1.f/S_);
    r.z=(az+bz)*(1.f/S_); r.w=(aw+bw)*(1.f/S_);
    reinterpret_cast<float4*>(g_pooled + (size_t)b*H_)[threadIdx.x] = r;
}

// ---------------- 2) router + top-4 + softmax --------------------------------
__global__ void __launch_bounds__(512) router_topk_kernel(const float* __restrict__ hid,
                                                          const float* __restrict__ rW,
                                                          const float* __restrict__ rb){
    __shared__ float cls[H_];
    __shared__ float lg[E_];
    int b = blockIdx.x, tid = threadIdx.x;
    cls[tid]       = hid[(size_t)b*S_*H_ + tid];
    cls[tid + 512] = hid[(size_t)b*S_*H_ + tid + 512];
    __syncthreads();
    int w = tid >> 5, lane = tid & 31;
    float s = 0.f;
    const float* wr = rW + w*H_;
    #pragma unroll 8
    for (int j=lane; j<H_; j+=32) s += cls[j]*wr[j];
    #pragma unroll
    for (int o=16;o>0;o>>=1) s += __shfl_xor_sync(0xffffffffu, s, o);
    if (lane==0) lg[w] = s + rb[w];
    __syncthreads();
    if (tid==0){
        float v[E_];
        #pragma unroll
        for (int i=0;i<E_;i++) v[i]=lg[i];
        int   idxs[K_]; float vals[K_];
        for (int k=0;k<K_;k++){
            int bi=0; float bv=-3.0e38f;
            #pragma unroll
            for (int i=0;i<E_;i++){ if (v[i]>bv){ bv=v[i]; bi=i; } }
            idxs[k]=bi; vals[k]=bv; v[bi]=-3.0e38f;
        }
        float m = vals[0], ssum=0.f, wv[K_];
        for (int k=0;k<K_;k++){ wv[k]=expf(vals[k]-m); ssum+=wv[k]; }
        float inv = 1.f/ssum;
        for (int k=0;k<K_;k++){ g_topi[b*K_+k]=idxs[k]; g_topw[b*K_+k]=wv[k]*inv; }
    }
}

// ---------------- 3) gather (single block, smem counters) --------------------
__global__ void __launch_bounds__(1024) gather_kernel(){
    __shared__ int cnt[E_];
    int t = threadIdx.x;
    if (t < E_) cnt[t] = 0;
    __syncthreads();
    #pragma unroll
    for (int i=0;i<4;i++){
        int idx = t + i*1024;
        int e = g_topi[idx];
        int pos = atomicAdd(&cnt[e], 1);
        g_tok [e*B_+pos] = idx >> 2;
        g_slot[e*B_+pos] = idx & 3;
    }
    __syncthreads();
    if (t < E_) g_cnt[t] = cnt[t];
}

// ---------------- 4) dense head: t = tanh(cls @ dW^T + db) -------------------
__global__ void __launch_bounds__(128) dense_tanh_kernel(const float* __restrict__ hid,
                                                         const float* __restrict__ W,
                                                         const float* __restrict__ bias){
    __shared__ float As[2][64*36];
    __shared__ float Bs[2][64*36];
    int t = threadIdx.x, lane = t & 31, warp = t >> 5;
    int wm = warp >> 1, wn = warp & 1;
    int m0 = blockIdx.y*64, n0 = blockIdx.x*64;
    int lr = t >> 3, lc = (t & 7)*4;
    float acc[2][4][4];
    #pragma unroll
    for (int i=0;i<2;i++)
        #pragma unroll
        for (int j=0;j<4;j++)
            #pragma unroll
            for (int k=0;k<4;k++) acc[i][j][k]=0.f;

    auto load = [&](int s, int k0){
        #pragma unroll
        for (int i=0;i<4;i++){
            int row = lr + 16*i;
            cp16(&As[s][row*36+lc], hid + (size_t)(m0+row)*S_*H_ + k0 + lc);
            cp16(&Bs[s][row*36+lc], W   + (size_t)(n0+row)*H_   + k0 + lc);
        }
    };
    load(0, 0); cp_commit();
    for (int it=0; it<32; it++){
        if (it+1 < 32){ load((it+1)&1, (it+1)*32); cp_commit(); cp_wait1(); }
        else cp_wait0();
        __syncthreads();
        compute_raw(As[it&1], Bs[it&1], wm*32, wn*32, lane, acc);
        __syncthreads();
    }
    int g = lane>>2, q = lane&3;
    #pragma unroll
    for (int nf=0;nf<4;nf++){
        int col = n0 + wn*32 + nf*8 + 2*q;
        float2 bb = *(const float2*)&bias[col];
        #pragma unroll
        for (int mf=0;mf<2;mf++){
            int row = m0 + wm*32 + mf*16 + g;
            float2 o0, o1;
            o0.x = tanhf(acc[mf][nf][0]+bb.x); o0.y = tanhf(acc[mf][nf][1]+bb.y);
            o1.x = tanhf(acc[mf][nf][2]+bb.x); o1.y = tanhf(acc[mf][nf][3]+bb.y);
            *(float2*)&g_t[(size_t)row*H_ + col]     = o0;
            *(float2*)&g_t[(size_t)(row+8)*H_ + col] = o1;
        }
    }
}

// ---------------- 5) orig = t @ out_W^T + out_b ------------------------------
__global__ void __launch_bounds__(256) orig_kernel(const float* __restrict__ oW,
                                                   const float* __restrict__ ob){
    int w = threadIdx.x >> 5, lane = threadIdx.x & 31;
    int b = blockIdx.x*8 + w;
    const float* t = g_t + (size_t)b*H_;
    for (int c=0;c<C_;c++){
        float s=0.f;
        const float* wr = oW + c*H_;
        #pragma unroll 8
        for (int j=lane; j<H_; j+=32) s += t[j]*wr[j];
        #pragma unroll
        for (int o=16;o>0;o>>=1) s += __shfl_xor_sync(0xffffffffu, s, o);
        if (lane==0) g_orig[b*C_+c] = s + ob[c];
    }
}

// ---------------- 6) fused expert: GEMM1 + LN + GELU + GEMM2 + proj ----------
// 16 gathered rows x 256 cols per block; 256 threads (8 warps, warp 16x32).
// Phase 1: K=1024 over eW1, C tile staged in smem, LN+GELU in place.
// Phase 2: K=256 over eW2 with A read straight from the smem tile; proj -> C=3.
__global__ void __launch_bounds__(256) expert_fused_kernel(const float* __restrict__ eW1,
                                                           const float* __restrict__ eb1,
                                                           const float* __restrict__ eg,
                                                           const float* __restrict__ ebt,
                                                           const float* __restrict__ eW2,
                                                           const float* __restrict__ eb2,
                                                           const float* __restrict__ pW,
                                                           const float* __restrict__ pb){
    extern __shared__ float sm[];
    float* As0 = sm;                    // 16*36
    float* As1 = sm + 576;
    float* Bs0 = sm + 1152;             // 256*36
    float* Bs1 = sm + 1152 + 9216;
    float* Cs  = sm + 19584;            // 16 x 260
    __shared__ int toks[16], slots[16];
    int e = blockIdx.y;
    int n = g_cnt[e];
    int r0 = blockIdx.x*16;
    if (r0 >= n) return;
    int t = threadIdx.x, lane = t & 31, warp = t >> 5;
    if (t < 16){
        int rc = min(r0 + t, n-1);
        toks[t]  = g_tok [e*B_+rc];
        slots[t] = g_slot[e*B_+rc];
    }
    __syncthreads();
    int lr = t >> 3, lc = (t & 7)*4;    // B rows lr+32i; A (t<128) row lr in 0..15
    float acc[4][4];
    #pragma unroll
    for (int i=0;i<4;i++)
        #pragma unroll
        for (int j=0;j<4;j++) acc[i][j]=0.f;

    const float* w1 = eW1 + (size_t)e*HE_*H_;
    const float* arow = g_pooled + (size_t)toks[lr & 15]*H_ + lc;
    auto load1 = [&](float* Asb, float* Bsb, int k0){
        if (t < 128) cp16(&Asb[lr*36+lc], arow + k0);
        #pragma unroll
        for (int i=0;i<8;i++){
            int row = lr + 32*i;
            cp16(&Bsb[row*36+lc], w1 + (size_t)row*H_ + k0 + lc);
        }
    };
    // ---- phase 1 mainloop (K=1024, 32 iters, 2-stage) ----
    load1(As0, Bs0, 0); cp_commit();
    for (int it=0; it<32; it++){
        if (it+1 < 32){
            if ((it+1)&1) load1(As1, Bs1, (it+1)*32); else load1(As0, Bs0, (it+1)*32);
            cp_commit(); cp_wait1();
        } else cp_wait0();
        __syncthreads();
        if (it&1) compute16<36>(As1, Bs1, warp*32, lane, acc);
        else      compute16<36>(As0, Bs0, warp*32, lane, acc);
        __syncthreads();
    }
    // ---- stage C tile into Cs ----
    int g = lane>>2, q = lane&3;
    #pragma unroll
    for (int nf=0;nf<4;nf++){
        int col = warp*32 + nf*8 + 2*q;
        float2 a; a.x=acc[nf][0]; a.y=acc[nf][1];
        float2 b; b.x=acc[nf][2]; b.y=acc[nf][3];
        *(float2*)&Cs[g*260 + col]     = a;
        *(float2*)&Cs[(g+8)*260 + col] = b;
    }
    __syncthreads();
    // ---- prefetch first eW2 tile while doing LN ----
    const float* w2 = eW2 + (size_t)e*HE_*HE_;
    auto load2 = [&](float* Bsb, int k0){
        #pragma unroll
        for (int i=0;i<8;i++){
            int row = lr + 32*i;
            cp16(&Bsb[row*36+lc], w2 + (size_t)row*HE_ + k0 + lc);
        }
    };
    load2(Bs0, 0); cp_commit();
    // ---- LN + GELU in place: 16 threads per row, 16 cols each ----
    {
        int row = t >> 4, j = t & 15;
        const float* b1 = eb1 + e*HE_;
        float s = 0.f, qs = 0.f;
        #pragma unroll
        for (int cc=0; cc<16; cc+=4){
            float4 v = *(float4*)&Cs[row*260 + j*16 + cc];
            float4 bb = *(const float4*)&b1[j*16 + cc];
            v.x+=bb.x; v.y+=bb.y; v.z+=bb.z; v.w+=bb.w;
            s  += v.x+v.y+v.z+v.w;
            qs += v.x*v.x+v.y*v.y+v.z*v.z+v.w*v.w;
        }
        #pragma unroll
        for (int o=1;o<16;o<<=1){
            s  += __shfl_xor_sync(0xffffffffu, s,  o);
            qs += __shfl_xor_sync(0xffffffffu, qs, o);
        }
        float m = s*(1.f/HE_);
        float var = qs*(1.f/HE_) - m*m;
        float rstd = rsqrtf(var + 1e-5f);
        const float* gp = eg  + e*HE_;
        const float* bp = ebt + e*HE_;
        #pragma unroll
        for (int cc=0; cc<16; cc+=4){
            float4 v = *(float4*)&Cs[row*260 + j*16 + cc];
            float4 bb = *(const float4*)&b1[j*16 + cc];
            float4 gg = *(const float4*)&gp[j*16 + cc];
            float4 bt = *(const float4*)&bp[j*16 + cc];
            float z0 = (v.x+bb.x-m)*rstd*gg.x + bt.x;
            float z1 = (v.y+bb.y-m)*rstd*gg.y + bt.y;
            float z2 = (v.z+bb.z-m)*rstd*gg.z + bt.z;
            float z3 = (v.w+bb.w-m)*rstd*gg.w + bt.w;
            float4 o;
            o.x = 0.5f*z0*(1.f+erff(z0*0.70710678118654752f));
            o.y = 0.5f*z1*(1.f+erff(z1*0.70710678118654752f));
            o.z = 0.5f*z2*(1.f+erff(z2*0.70710678118654752f));
            o.w = 0.5f*z3*(1.f+erff(z3*0.70710678118654752f));
            *(float4*)&Cs[row*260 + j*16 + cc] = o;
        }
    }
    __syncthreads();
    // ---- phase 2 mainloop (K=256, 8 iters, 2-stage; A = Cs, stride 260) ----
    float acc2[4][4];
    #pragma unroll
    for (int i=0;i<4;i++)
        #pragma unroll
        for (int j=0;j<4;j++) acc2[i][j]=0.f;
    for (int it=0; it<8; it++){
        if (it+1 < 8){
            if ((it+1)&1) load2(Bs1, (it+1)*32); else load2(Bs0, (it+1)*32);
            cp_commit(); cp_wait1();
        } else cp_wait0();
        __syncthreads();
        if (it&1) compute16<260>(Cs + it*32, Bs1, warp*32, lane, acc2);
        else      compute16<260>(Cs + it*32, Bs0, warp*32, lane, acc2);
        __syncthreads();
    }
    // ---- stage phase-2 C tile (overwrite Cs; loop ended with a sync) ----
    #pragma unroll
    for (int nf=0;nf<4;nf++){
        int col = warp*32 + nf*8 + 2*q;
        float2 a; a.x=acc2[nf][0]; a.y=acc2[nf][1];
        float2 b; b.x=acc2[nf][2]; b.y=acc2[nf][3];
        *(float2*)&Cs[g*260 + col]     = a;
        *(float2*)&Cs[(g+8)*260 + col] = b;
    }
    __syncthreads();
    // ---- proj epilogue: 16 threads/row, 16 cols each -> C=3 ----
    {
        int row = t >> 4, j = t & 15;
        int gr = r0 + row;
        const float* b2 = eb2 + e*HE_;
        float p0=0.f, p1=0.f, p2=0.f;
        #pragma unroll
        for (int cc=0; cc<16; cc+=4){
            float4 v = *(float4*)&Cs[row*260 + j*16 + cc];
            float4 bb = *(const float4*)&b2[j*16 + cc];
            v.x+=bb.x; v.y+=bb.y; v.z+=bb.z; v.w+=bb.w;
            float4 w0 = *(const float4*)&pW[0*HE_ + j*16 + cc];
            float4 w1p = *(const float4*)&pW[1*HE_ + j*16 + cc];
            float4 w2p = *(const float4*)&pW[2*HE_ + j*16 + cc];
            p0 += v.x*w0.x + v.y*w0.y + v.z*w0.z + v.w*w0.w;
            p1 += v.x*w1p.x + v.y*w1p.y + v.z*w1p.z + v.w*w1p.w;
            p2 += v.x*w2p.x + v.y*w2p.y + v.z*w2p.z + v.w*w2p.w;
        }
        #pragma unroll
        for (int o=1;o<16;o<<=1){
            p0 += __shfl_xor_sync(0xffffffffu, p0, o);
            p1 += __shfl_xor_sync(0xffffffffu, p1, o);
            p2 += __shfl_xor_sync(0xffffffffu, p2, o);
        }
        if (j == 0 && gr < n){
            int b = toks[row], sl = slots[row];
            float* o = &g_el[(b*K_+sl)*C_];
            o[0] = p0 + pb[0];
            o[1] = p1 + pb[1];
            o[2] = p2 + pb[2];
        }
    }
}

// ---------------- 8) final head ---------------------------------------------
__global__ void __launch_bounds__(256) final_kernel(const float* __restrict__ f1W,
                                                    const float* __restrict__ f1b,
                                                    const float* __restrict__ fg,
                                                    const float* __restrict__ fbt,
                                                    const float* __restrict__ f2W,
                                                    const float* __restrict__ f2b,
                                                    float* __restrict__ out){
    int b = blockIdx.x*blockDim.x + threadIdx.x;
    if (b >= B_) return;
    float comb[2*C_];
    #pragma unroll
    for (int c=0;c<C_;c++) comb[c] = g_orig[b*C_+c];
    float moe[C_]={0.f,0.f,0.f};
    #pragma unroll
    for (int k=0;k<K_;k++){
        float w = g_topw[b*K_+k];
        const float* el = &g_el[(b*K_+k)*C_];
        #pragma unroll
        for (int c=0;c<C_;c++) moe[c] += w*el[c];
    }
    #pragma unroll
    for (int c=0;c<C_;c++) comb[C_+c]=moe[c];
    float y[C_];
    #pragma unroll
    for (int c=0;c<C_;c++){
        float s = f1b[c];
        #pragma unroll
        for (int jj=0;jj<2*C_;jj++) s += comb[jj]*f1W[c*(2*C_)+jj];
        y[c]=s;
    }
    float m = (y[0]+y[1]+y[2])*(1.f/3.f);
    float d0=y[0]-m, d1=y[1]-m, d2=y[2]-m;
    float var = (d0*d0+d1*d1+d2*d2)*(1.f/3.f);
    float rs = rsqrtf(var + 1e-5f);
    float z[C_];
    #pragma unroll
    for (int c=0;c<C_;c++) z[c] = fmaxf(0.f, (y[c]-m)*rs*fg[c] + fbt[c]);
    #pragma unroll
    for (int c2=0;c2<C_;c2++){
        float s = f2b[c2];
        #pragma unroll
        for (int c=0;c<C_;c++) s += z[c]*f2W[c2*C_+c];
        out[b*C_+c2] = s;
    }
}

// ---------------- streams/events (host-side objects, created once) -----------
struct SideStreams {
    cudaStream_t sB, sC;
    cudaEvent_t  evFork, evJB, evJC;
    SideStreams(){
        cudaStreamCreateWithFlags(&sB, cudaStreamNonBlocking);
        cudaStreamCreateWithFlags(&sC, cudaStreamNonBlocking);
        cudaEventCreateWithFlags(&evFork, cudaEventDisableTiming);
        cudaEventCreateWithFlags(&evJB,   cudaEventDisableTiming);
        cudaEventCreateWithFlags(&evJC,   cudaEventDisableTiming);
    }
};
static SideStreams g_ss;

// ---------------- launch -----------------------------------------------------
extern "C" void kernel_launch(void* const* d_in, const int* in_sizes, int n_in,
                              void* d_out, int out_size){
    const float* hid = (const float*)d_in[0];
    const float* rW  = (const float*)d_in[1];
    const float* rb  = (const float*)d_in[2];
    const float* eW1 = (const float*)d_in[3];
    const float* eb1 = (const float*)d_in[4];
    const float* eg  = (const float*)d_in[5];
    const float* ebt = (const float*)d_in[6];
    const float* eW2 = (const float*)d_in[7];
    const float* eb2 = (const float*)d_in[8];
    const float* pW  = (const float*)d_in[9];
    const float* pb  = (const float*)d_in[10];
    const float* dW  = (const float*)d_in[11];
    const float* db  = (const float*)d_in[12];
    const float* oW  = (const float*)d_in[13];
    const float* ob  = (const float*)d_in[14];
    const float* f1W = (const float*)d_in[15];
    const float* f1b = (const float*)d_in[16];
    const float* fg  = (const float*)d_in[17];
    const float* fbt = (const float*)d_in[18];
    const float* f2W = (const float*)d_in[19];
    const float* f2b = (const float*)d_in[20];
    float* out = (float*)d_out;

    const int DSM_EXP = (2*16*36 + 2*256*36 + 16*260)*4;  // 94976 B
    cudaFuncSetAttribute(expert_fused_kernel, cudaFuncAttributeMaxDynamicSharedMemorySize, DSM_EXP);

    // fork branches
    cudaEventRecord(g_ss.evFork, 0);
    cudaStreamWaitEvent(g_ss.sB, g_ss.evFork, 0);
    cudaStreamWaitEvent(g_ss.sC, g_ss.evFork, 0);

    // main stream: HBM-bound pool (critical path)
    pool_kernel<<<B_, 256>>>(hid);

    // branch B: router + gather
    router_topk_kernel<<<B_, 512, 0, g_ss.sB>>>(hid, rW, rb);
    gather_kernel<<<1, 1024, 0, g_ss.sB>>>();
    cudaEventRecord(g_ss.evJB, g_ss.sB);

    // branch C: dense head + orig
    dense_tanh_kernel<<<dim3(16,16), 128, 0, g_ss.sC>>>(hid, dW, db);
    orig_kernel<<<B_/8, 256, 0, g_ss.sC>>>(oW, ob);
    cudaEventRecord(g_ss.evJC, g_ss.sC);

    // join B before fused expert kernel
    cudaStreamWaitEvent(0, g_ss.evJB, 0);
    expert_fused_kernel<<<dim3(B_/16, E_), 256, DSM_EXP>>>(eW1, eb1, eg, ebt,
                                                           eW2, eb2, pW, pb);

    // join C before final head
    cudaStreamWaitEvent(0, g_ss.evJC, 0);
    final_kernel<<<B_/256, 256>>>(f1W, f1b, fg, fbt, f2W, f2b, out);
}